// round 12
// baseline (speedup 1.0000x reference)
#include <cuda_runtime.h>
#include <cuda_fp16.h>
#include <mma.h>
#include <cstdint>

using namespace nvcuda;

#define NPOL 20000
#define NSTK 10000
#define EDG  400000
#define HID  512
#define NC   3

// padded row counts (multiples of 128): no bounds checks in GEMM epilogues
#define PROWS 20096
#define SROWS 10112

#define WBIG (512 * 512)
#define WSML (64 * 512)

// ---------------- device scratch (fp16 activation buffers, reused across stages) ----
__device__ __half g_pA[(size_t)PROWS * HID];   // hp0 -> hp2
__device__ __half g_pB[(size_t)PROWS * HID];   // hp1 -> A
__device__ __half g_pC[(size_t)PROWS * HID];   // mean_sp(tmp)
__device__ __half g_sA[(size_t)SROWS * HID];   // hs0 -> hs2
__device__ __half g_sB[(size_t)SROWS * HID];   // hs1 -> B
__device__ __half g_sC[(size_t)SROWS * HID];   // mean_ps
__device__ __half g_sD[(size_t)SROWS * HID];   // tmp (hs @ sp_Wl)

__device__ __half g_w16[10 * WBIG + 2 * WSML];
__device__ __half g_xp16[(size_t)NPOL * 64];
__device__ __half g_xs16[(size_t)NSTK * 64];

__device__ int g_cnt_ps[NSTK];
__device__ int g_off_ps[NSTK + 1];
__device__ int g_cur_ps[NSTK];
__device__ int g_src_ps[EDG];

__device__ int g_cnt_sp[NPOL];
__device__ int g_off_sp[NPOL + 1];
__device__ int g_cur_sp[NPOL];
__device__ int g_src_sp[EDG];

// ---------------- f32 -> f16 converts (weights + raw inputs) ----------------
struct CPack {
    const float* src[14];
    __half*      dst[14];
    int          cnt[14];
};

__global__ __launch_bounds__(256) void convert_all_kernel(CPack p) {
    int s = blockIdx.y;
    const float4* src = reinterpret_cast<const float4*>(p.src[s]);
    __half2* dst = reinterpret_cast<__half2*>(p.dst[s]);
    int n4 = p.cnt[s] >> 2;
    for (int i = blockIdx.x * blockDim.x + threadIdx.x; i < n4; i += gridDim.x * blockDim.x) {
        float4 v = src[i];
        dst[2 * i]     = __floats2half2_rn(v.x, v.y);
        dst[2 * i + 1] = __floats2half2_rn(v.z, v.w);
    }
}

// ---------------- CSR build ----------------
__global__ void zero2_kernel(int* a, int na, int* b, int nb) {
    int i  = blockIdx.x * blockDim.x + threadIdx.x;
    int st = gridDim.x * blockDim.x;
    for (int j = i; j < na; j += st) a[j] = 0;
    for (int j = i; j < nb; j += st) b[j] = 0;
}

__global__ void histo2_kernel(const int* __restrict__ d0, int* c0,
                              const int* __restrict__ d1, int* c1, int n) {
    int i  = blockIdx.x * blockDim.x + threadIdx.x;
    int st = gridDim.x * blockDim.x;
    for (int e = i; e < n; e += st) {
        atomicAdd(&c0[d0[e]], 1);
        atomicAdd(&c1[d1[e]], 1);
    }
}

// warp-shuffle scan: 4 block barriers per 1024-tile
__global__ __launch_bounds__(1024) void exscan2_kernel(
    const int* __restrict__ cnt0, int n0, int* off0, int* cur0,
    const int* __restrict__ cnt1, int n1, int* off1, int* cur1) {
    const int* cnt = blockIdx.x ? cnt1 : cnt0;
    int  n   = blockIdx.x ? n1 : n0;
    int* off = blockIdx.x ? off1 : off0;
    int* cur = blockIdx.x ? cur1 : cur0;

    __shared__ int sWarp[32];
    __shared__ int sTotal;
    __shared__ int sCarry;
    int tid  = threadIdx.x;
    int wid  = tid >> 5;
    int lane = tid & 31;
    if (tid == 0) sCarry = 0;
    __syncthreads();

    for (int base = 0; base < n; base += 1024) {
        int i = base + tid;
        int v = (i < n) ? cnt[i] : 0;
        int incl = v;
        #pragma unroll
        for (int o = 1; o < 32; o <<= 1) {
            int t = __shfl_up_sync(0xffffffffu, incl, o);
            if (lane >= o) incl += t;
        }
        if (lane == 31) sWarp[wid] = incl;
        __syncthreads();
        if (wid == 0) {
            int wv = sWarp[lane];
            int wi = wv;
            #pragma unroll
            for (int o = 1; o < 32; o <<= 1) {
                int t = __shfl_up_sync(0xffffffffu, wi, o);
                if (lane >= o) wi += t;
            }
            sWarp[lane] = wi - wv;
            if (lane == 31) sTotal = wi;
        }
        __syncthreads();
        int carry = sCarry;
        if (i < n) {
            int ex = carry + sWarp[wid] + incl - v;
            off[i] = ex;
            cur[i] = ex;
        }
        __syncthreads();
        if (tid == 0) sCarry = carry + sTotal;
        __syncthreads();
    }
    if (tid == 0) off[n] = sCarry;
}

__global__ void scatter2_kernel(const int* __restrict__ s0, const int* __restrict__ dd0,
                                int* cur0, int* o0,
                                const int* __restrict__ s1, const int* __restrict__ dd1,
                                int* cur1, int* o1, int n) {
    int i  = blockIdx.x * blockDim.x + threadIdx.x;
    int st = gridDim.x * blockDim.x;
    for (int e = i; e < n; e += st) {
        int p0 = atomicAdd(&cur0[dd0[e]], 1);
        o0[p0] = s0[e];
        int p1 = atomicAdd(&cur1[dd1[e]], 1);
        o1[p1] = s1[e];
    }
}

// ---------------- mean aggregation over CSR, merged pair (fp16 in/out, fp32 accum) ----
__global__ __launch_bounds__(128) void agg_mean2_kernel(
    const __half* __restrict__ X0, const int* __restrict__ off0,
    const int* __restrict__ srcs0, __half* __restrict__ out0, int nd0,
    const __half* __restrict__ X1, const int* __restrict__ off1,
    const int* __restrict__ srcs1, __half* __restrict__ out1) {
    const bool first = (int)blockIdx.x < nd0;
    const __half* X  = first ? X0 : X1;
    const int* off   = first ? off0 : off1;
    const int* srcs  = first ? srcs0 : srcs1;
    __half* out      = first ? out0 : out1;
    int d = first ? blockIdx.x : (blockIdx.x - nd0);

    int tid = threadIdx.x;
    int beg = off[d];
    int end = off[d + 1];

    __shared__ int sIdx[128];
    float a0 = 0.f, a1 = 0.f, a2 = 0.f, a3 = 0.f;

    for (int cb = beg; cb < end; cb += 128) {
        int m = min(128, end - cb);
        if (tid < m) sIdx[tid] = srcs[cb + tid];
        __syncthreads();
        int j = 0;
        for (; j + 4 <= m; j += 4) {
            uint2 v0 = reinterpret_cast<const uint2*>(X + (size_t)sIdx[j]     * HID)[tid];
            uint2 v1 = reinterpret_cast<const uint2*>(X + (size_t)sIdx[j + 1] * HID)[tid];
            uint2 v2 = reinterpret_cast<const uint2*>(X + (size_t)sIdx[j + 2] * HID)[tid];
            uint2 v3 = reinterpret_cast<const uint2*>(X + (size_t)sIdx[j + 3] * HID)[tid];
            float2 f;
            f = __half22float2(*reinterpret_cast<__half2*>(&v0.x)); a0 += f.x; a1 += f.y;
            f = __half22float2(*reinterpret_cast<__half2*>(&v0.y)); a2 += f.x; a3 += f.y;
            f = __half22float2(*reinterpret_cast<__half2*>(&v1.x)); a0 += f.x; a1 += f.y;
            f = __half22float2(*reinterpret_cast<__half2*>(&v1.y)); a2 += f.x; a3 += f.y;
            f = __half22float2(*reinterpret_cast<__half2*>(&v2.x)); a0 += f.x; a1 += f.y;
            f = __half22float2(*reinterpret_cast<__half2*>(&v2.y)); a2 += f.x; a3 += f.y;
            f = __half22float2(*reinterpret_cast<__half2*>(&v3.x)); a0 += f.x; a1 += f.y;
            f = __half22float2(*reinterpret_cast<__half2*>(&v3.y)); a2 += f.x; a3 += f.y;
        }
        for (; j < m; j++) {
            uint2 v = reinterpret_cast<const uint2*>(X + (size_t)sIdx[j] * HID)[tid];
            float2 f;
            f = __half22float2(*reinterpret_cast<__half2*>(&v.x)); a0 += f.x; a1 += f.y;
            f = __half22float2(*reinterpret_cast<__half2*>(&v.y)); a2 += f.x; a3 += f.y;
        }
        __syncthreads();
    }
    float inv = (end > beg) ? 1.0f / (float)(end - beg) : 0.0f;
    uint2 ov;
    *reinterpret_cast<__half2*>(&ov.x) = __floats2half2_rn(a0 * inv, a1 * inv);
    *reinterpret_cast<__half2*>(&ov.y) = __floats2half2_rn(a2 * inv, a3 * inv);
    reinterpret_cast<uint2*>(out + (size_t)d * HID)[tid] = ov;
}

// ---------------- cp.async helpers ----------------
__device__ __forceinline__ void cp_async16(void* dst, const void* src, bool pred) {
    uint32_t s = (uint32_t)__cvta_generic_to_shared(dst);
    int n = pred ? 16 : 0;
    asm volatile("cp.async.cg.shared.global [%0], [%1], 16, %2;\n" :: "r"(s), "l"(src), "r"(n));
}
__device__ __forceinline__ void cp_commit() { asm volatile("cp.async.commit_group;\n"); }
template <int N>
__device__ __forceinline__ void cp_wait() { asm volatile("cp.async.wait_group %0;\n" :: "n"(N)); }

// ---------------- fp16 WMMA GEMM (dual-problem), fp16 output ----------------
// BM=128, BN=128, BK=64, 256 threads (8 warps; warp tile 32x64 = 2x4 m16n16k16)
// 3-stage cp.async pipeline, one __syncthreads per 64-wide chunk (half the barriers of BK=32).
// dynamic smem: Xs 3x128x72h (55296) | Ws 3x64x136h (52224) | bias 512 = 108032.
// f32 epilogue staging ALIASES the Xs region (dead after main loop; barrier guards reuse).
#define XLDH 72
#define WLDH 136
#define SLDF 20
#define SMO_XS    0
#define SMO_WS    55296
#define SMO_BIAS  107520
#define SMG_TOT   108032

struct GProb {
    const __half* X0; const __half* W0;
    const __half* X1; const __half* W1;
    const float*  bias; const __half* C0;
    __half* C;
    int M, K, npair, dorelu;
};

__global__ __launch_bounds__(256) void gemm_fp16_dual(GProb pa, GProb pb, int split) {
    extern __shared__ __align__(16) char dsm[];
    __half (*Xs)[128][XLDH] = reinterpret_cast<__half(*)[128][XLDH]>(dsm + SMO_XS);
    __half (*Ws)[64][WLDH]  = reinterpret_cast<__half(*)[64][WLDH]>(dsm + SMO_WS);
    float* s_bias = reinterpret_cast<float*>(dsm + SMO_BIAS);

    const bool  first = (int)blockIdx.x < split;
    const GProb P     = first ? pa : pb;
    const int   bx    = first ? blockIdx.x : (blockIdx.x - split);

    const int row0 = bx * 128;
    const int n0   = blockIdx.y * 128;
    const int tid  = threadIdx.x;
    const int warp = tid >> 5;
    const int lane = tid & 31;
    const int wm   = warp >> 1;   // 0..3
    const int wn   = warp & 1;    // 0..1

    if (tid < 128) s_bias[tid] = P.bias ? P.bias[n0 + tid] : 0.0f;

    wmma::fragment<wmma::accumulator, 16, 16, 16, float> acc[2][4];
    #pragma unroll
    for (int i = 0; i < 2; i++)
        #pragma unroll
        for (int j = 0; j < 4; j++)
            wmma::fill_fragment(acc[i][j], 0.0f);

    const int CK = P.K >> 6;            // 64-wide chunks per pair
    const int T  = P.npair * CK;
    const int K  = P.K;
    const int M  = P.M;

    auto load_chunk = [&](int c, int buf) {
        int pair = (c >= CK) ? 1 : 0;
        const __half* X = pair ? P.X1 : P.X0;
        const __half* W = pair ? P.W1 : P.W0;
        int kk = (c - pair * CK) * 64;
        // A tile: 128 rows x 64 halves = 1024 16B units
        #pragma unroll
        for (int q = 0; q < 4; q++) {
            int u = tid + q * 256;
            int r = u >> 3, cu = u & 7;
            int rg = row0 + r;
            cp_async16(&Xs[buf][r][cu * 8], X + (size_t)rg * K + kk + cu * 8, rg < M);
        }
        // B tile: 64 rows x 128 halves = 1024 units
        #pragma unroll
        for (int q = 0; q < 4; q++) {
            int u = tid + q * 256;
            int r = u >> 4, cu = u & 15;
            cp_async16(&Ws[buf][r][cu * 8], W + (size_t)(kk + r) * HID + n0 + cu * 8, true);
        }
        cp_commit();
    };

    auto compute = [&](int buf) {
        #pragma unroll
        for (int kk = 0; kk < 64; kk += 16) {
            wmma::fragment<wmma::matrix_a, 16, 16, 16, __half, wmma::row_major> a[2];
            wmma::fragment<wmma::matrix_b, 16, 16, 16, __half, wmma::row_major> b[4];
            #pragma unroll
            for (int i = 0; i < 2; i++)
                wmma::load_matrix_sync(a[i], &Xs[buf][wm * 32 + i * 16][kk], XLDH);
            #pragma unroll
            for (int j = 0; j < 4; j++)
                wmma::load_matrix_sync(b[j], &Ws[buf][kk][wn * 64 + j * 16], WLDH);
            #pragma unroll
            for (int i = 0; i < 2; i++)
                #pragma unroll
                for (int j = 0; j < 4; j++)
                    wmma::mma_sync(acc[i][j], a[i], b[j], acc[i][j]);
        }
    };

    // 3-stage pipeline: prefetch up to 2 chunks, one barrier per chunk.
    load_chunk(0, 0);
    if (T > 1) load_chunk(1, 1);
    int b3 = 0;                        // c % 3 tracker (avoid divides)
    for (int t = 0; t < T; t++) {
        if (t + 1 < T) cp_wait<1>(); else cp_wait<0>();
        __syncthreads();
        compute(b3);
        // writing buffer (t+2)%3 == (t-1)%3: consumed before the barrier above
        if (t + 2 < T) {
            int nb = b3 + 2; if (nb >= 3) nb -= 3;
            load_chunk(t + 2, nb);
        }
        if (++b3 == 3) b3 = 0;
    }

    // epilogue: staging aliases Xs — barrier so all warps are done with smem tiles
    __syncthreads();
    float* stw = reinterpret_cast<float*>(dsm) + warp * (16 * SLDF);
    const int lr = lane >> 1;
    const int lc = (lane & 1) * 8;
    #pragma unroll
    for (int i = 0; i < 2; i++) {
        #pragma unroll
        for (int j = 0; j < 4; j++) {
            wmma::store_matrix_sync(stw, acc[i][j], SLDF, wmma::mem_row_major);
            __syncwarp();
            int grow = row0 + wm * 32 + i * 16 + lr;
            int bcol = wn * 64 + j * 16 + lc;
            const float* sp = stw + lr * SLDF + lc;
            float v[8];
            #pragma unroll
            for (int t = 0; t < 8; t++) v[t] = sp[t] + s_bias[bcol + t];
            if (P.C0) {
                uint4 cz = *reinterpret_cast<const uint4*>(P.C0 + (size_t)grow * HID + n0 + bcol);
                float2 c0 = __half22float2(*reinterpret_cast<__half2*>(&cz.x));
                float2 c1 = __half22float2(*reinterpret_cast<__half2*>(&cz.y));
                float2 c2 = __half22float2(*reinterpret_cast<__half2*>(&cz.z));
                float2 c3 = __half22float2(*reinterpret_cast<__half2*>(&cz.w));
                v[0] += c0.x; v[1] += c0.y; v[2] += c1.x; v[3] += c1.y;
                v[4] += c2.x; v[5] += c2.y; v[6] += c3.x; v[7] += c3.y;
            }
            if (P.dorelu) {
                #pragma unroll
                for (int t = 0; t < 8; t++) v[t] = fmaxf(v[t], 0.0f);
            }
            uint4 ov;
            *reinterpret_cast<__half2*>(&ov.x) = __floats2half2_rn(v[0], v[1]);
            *reinterpret_cast<__half2*>(&ov.y) = __floats2half2_rn(v[2], v[3]);
            *reinterpret_cast<__half2*>(&ov.z) = __floats2half2_rn(v[4], v[5]);
            *reinterpret_cast<__half2*>(&ov.w) = __floats2half2_rn(v[6], v[7]);
            *reinterpret_cast<uint4*>(P.C + (size_t)grow * HID + n0 + bcol) = ov;
            __syncwarp();
        }
    }
}

// ---------------- fused per-edge decoder (fp16 A/B, fp32 math) ----------------
__global__ __launch_bounds__(256) void edge_decode_kernel(
    const __half* __restrict__ Aa, const __half* __restrict__ Bb,
    const float* __restrict__ attr,
    const float* __restrict__ w0, const float* __restrict__ w1,
    const float* __restrict__ b1,
    const float* __restrict__ d2W, const float* __restrict__ d2b,
    const int* __restrict__ erow, const int* __restrict__ ecol,
    float* __restrict__ out) {
    __shared__ float4 s_w0[128], s_w1[128], s_b[128], s_d0[128], s_d1[128], s_d2[128];
    int tid = threadIdx.x;
    for (int i = tid; i < HID; i += 256) {
        ((float*)s_w0)[i] = w0[i];
        ((float*)s_w1)[i] = w1[i];
        ((float*)s_b)[i]  = b1[i];
        ((float*)s_d0)[i] = d2W[i * 3 + 0];
        ((float*)s_d1)[i] = d2W[i * 3 + 1];
        ((float*)s_d2)[i] = d2W[i * 3 + 2];
    }
    __syncthreads();
    float db0 = d2b[0], db1 = d2b[1], db2 = d2b[2];
    int lane = tid & 31;
    int warp = tid >> 5;

    for (int e = blockIdx.x * 8 + warp; e < EDG; e += gridDim.x * 8) {
        int r = erow[e];
        int c = ecol[e];
        float a0 = attr[2 * e];
        float a1 = attr[2 * e + 1];
        const uint2* A4 = reinterpret_cast<const uint2*>(Aa + (size_t)r * HID);
        const uint2* B4 = reinterpret_cast<const uint2*>(Bb + (size_t)c * HID);
        float s0 = 0.f, s1 = 0.f, s2 = 0.f;
        #pragma unroll
        for (int k = 0; k < 4; k++) {
            int q = k * 32 + lane;
            uint2 au = A4[q], bu = B4[q];
            float2 a01 = __half22float2(*reinterpret_cast<__half2*>(&au.x));
            float2 a23 = __half22float2(*reinterpret_cast<__half2*>(&au.y));
            float2 b01 = __half22float2(*reinterpret_cast<__half2*>(&bu.x));
            float2 b23 = __half22float2(*reinterpret_cast<__half2*>(&bu.y));
            float4 va = make_float4(a01.x, a01.y, a23.x, a23.y);
            float4 vb = make_float4(b01.x, b01.y, b23.x, b23.y);
            float4 vw0 = s_w0[q], vw1 = s_w1[q], vbb = s_b[q];
            float4 v0 = s_d0[q], v1 = s_d1[q], v2 = s_d2[q];
            float h;
            h = fmaxf(va.x + vb.x + a0 * vw0.x + a1 * vw1.x + vbb.x, 0.f);
            s0 += h * v0.x; s1 += h * v1.x; s2 += h * v2.x;
            h = fmaxf(va.y + vb.y + a0 * vw0.y + a1 * vw1.y + vbb.y, 0.f);
            s0 += h * v0.y; s1 += h * v1.y; s2 += h * v2.y;
            h = fmaxf(va.z + vb.z + a0 * vw0.z + a1 * vw1.z + vbb.z, 0.f);
            s0 += h * v0.z; s1 += h * v1.z; s2 += h * v2.z;
            h = fmaxf(va.w + vb.w + a0 * vw0.w + a1 * vw1.w + vbb.w, 0.f);
            s0 += h * v0.w; s1 += h * v1.w; s2 += h * v2.w;
        }
        #pragma unroll
        for (int o = 16; o > 0; o >>= 1) {
            s0 += __shfl_xor_sync(0xffffffffu, s0, o);
            s1 += __shfl_xor_sync(0xffffffffu, s1, o);
            s2 += __shfl_xor_sync(0xffffffffu, s2, o);
        }
        if (lane == 0) {
            out[(size_t)e * 3 + 0] = s0 + db0;
            out[(size_t)e * 3 + 1] = s1 + db1;
            out[(size_t)e * 3 + 2] = s2 + db2;
        }
    }
}

// ---------------- host launch ----------------
extern "C" void kernel_launch(void* const* d_in, const int* in_sizes, int n_in,
                              void* d_out, int out_size) {
    (void)in_sizes; (void)n_in; (void)out_size;

    const float* x_pol = (const float*)d_in[0];
    const float* x_stk = (const float*)d_in[1];
    const float* attr  = (const float*)d_in[2];
    const float* Wp    = (const float*)d_in[3];
    const float* bp    = (const float*)d_in[4];
    const float* Ws    = (const float*)d_in[5];
    const float* bs    = (const float*)d_in[6];
    const float* c1_ps_Wl = (const float*)d_in[7];
    const float* c1_ps_bl = (const float*)d_in[8];
    const float* c1_ps_Wr = (const float*)d_in[9];
    const float* c1_sp_Wl = (const float*)d_in[10];
    const float* c1_sp_bl = (const float*)d_in[11];
    const float* c1_sp_Wr = (const float*)d_in[12];
    const float* c2_ps_Wl = (const float*)d_in[13];
    const float* c2_ps_bl = (const float*)d_in[14];
    const float* c2_ps_Wr = (const float*)d_in[15];
    const float* c2_sp_Wl = (const float*)d_in[16];
    const float* c2_sp_bl = (const float*)d_in[17];
    const float* c2_sp_Wr = (const float*)d_in[18];
    const float* d1_W  = (const float*)d_in[19];   // [1026, 512]
    const float* d1_b  = (const float*)d_in[20];
    const float* d2_W  = (const float*)d_in[21];   // [512, 3]
    const float* d2_b  = (const float*)d_in[22];
    const int* eps_src = (const int*)d_in[23];
    const int* eps_dst = (const int*)d_in[24];
    const int* esp_src = (const int*)d_in[25];
    const int* esp_dst = (const int*)d_in[26];
    const int* trow    = (const int*)d_in[27];
    const int* tcol    = (const int*)d_in[28];
    float* out = (float*)d_out;

    void* p;
    cudaGetSymbolAddress(&p, g_pA);     __half* pA = (__half*)p;
    cudaGetSymbolAddress(&p, g_pB);     __half* pB = (__half*)p;
    cudaGetSymbolAddress(&p, g_pC);     __half* pC = (__half*)p;
    cudaGetSymbolAddress(&p, g_sA);     __half* sA = (__half*)p;
    cudaGetSymbolAddress(&p, g_sB);     __half* sB = (__half*)p;
    cudaGetSymbolAddress(&p, g_sC);     __half* sC = (__half*)p;
    cudaGetSymbolAddress(&p, g_sD);     __half* sD = (__half*)p;
    cudaGetSymbolAddress(&p, g_w16);    __half* w16 = (__half*)p;
    cudaGetSymbolAddress(&p, g_xp16);   __half* xp16 = (__half*)p;
    cudaGetSymbolAddress(&p, g_xs16);   __half* xs16 = (__half*)p;
    cudaGetSymbolAddress(&p, g_cnt_ps); int* cnt_ps = (int*)p;
    cudaGetSymbolAddress(&p, g_off_ps); int* off_ps = (int*)p;
    cudaGetSymbolAddress(&p, g_cur_ps); int* cur_ps = (int*)p;
    cudaGetSymbolAddress(&p, g_src_ps); int* src_ps = (int*)p;
    cudaGetSymbolAddress(&p, g_cnt_sp); int* cnt_sp = (int*)p;
    cudaGetSymbolAddress(&p, g_off_sp); int* off_sp = (int*)p;
    cudaGetSymbolAddress(&p, g_cur_sp); int* cur_sp = (int*)p;
    cudaGetSymbolAddress(&p, g_src_sp); int* src_sp = (int*)p;

    cudaFuncSetAttribute(gemm_fp16_dual, cudaFuncAttributeMaxDynamicSharedMemorySize, SMG_TOT);

    // fp16 weight table
    __half* w[12];
    const float* wsrc[12] = {c1_ps_Wl, c1_ps_Wr, c1_sp_Wl, c1_sp_Wr,
                             c2_ps_Wl, c2_ps_Wr, c2_sp_Wl, c2_sp_Wr,
                             d1_W, d1_W + (size_t)512 * HID, Wp, Ws};
    for (int i = 0; i < 10; i++) w[i] = w16 + (size_t)i * WBIG;
    w[10] = w16 + (size_t)10 * WBIG;
    w[11] = w16 + (size_t)10 * WBIG + WSML;

    CPack cp;
    for (int i = 0; i < 12; i++) { cp.src[i] = wsrc[i]; cp.dst[i] = w[i]; cp.cnt[i] = (i < 10) ? WBIG : WSML; }
    cp.src[12] = x_pol; cp.dst[12] = xp16; cp.cnt[12] = NPOL * 64;
    cp.src[13] = x_stk; cp.dst[13] = xs16; cp.cnt[13] = NSTK * 64;

    const int PB = PROWS / 128;   // 157
    const int SB = SROWS / 128;   // 79

    auto prob = [](const __half* X0, const __half* W0, const __half* X1, const __half* W1,
                   const float* bias, const __half* C0, __half* C,
                   int M, int K, int npair, int dorelu) {
        GProb g; g.X0 = X0; g.W0 = W0; g.X1 = X1; g.W1 = W1;
        g.bias = bias; g.C0 = C0; g.C = C; g.M = M; g.K = K; g.npair = npair; g.dorelu = dorelu;
        return g;
    };

    // converts + CSR front
    convert_all_kernel<<<dim3(256, 14), 256>>>(cp);
    zero2_kernel<<<64, 256>>>(cnt_ps, NSTK, cnt_sp, NPOL);
    histo2_kernel<<<400, 256>>>(eps_dst, cnt_ps, esp_dst, cnt_sp, EDG);

    // projections (merged) — launch slot 4 for ncu
    {
        GProb a = prob(xp16, w[10], nullptr, nullptr, bp, nullptr, pA, NPOL, 64, 1, 1);
        GProb b = prob(xs16, w[11], nullptr, nullptr, bs, nullptr, sA, NSTK, 64, 1, 1);
        gemm_fp16_dual<<<dim3(PB + SB, 4), 256, SMG_TOT>>>(a, b, PB);
    }

    // finish CSR
    exscan2_kernel<<<2, 1024>>>(cnt_ps, NSTK, off_ps, cur_ps, cnt_sp, NPOL, off_sp, cur_sp);
    scatter2_kernel<<<400, 256>>>(eps_src, eps_dst, cur_ps, src_ps,
                                  esp_src, esp_dst, cur_sp, src_sp, EDG);

    // ---- layer 1 ----
    {
        GProb a = prob(sA, w[2], nullptr, nullptr, nullptr, nullptr, sD, NSTK, 512, 1, 0);
        gemm_fp16_dual<<<dim3(SB, 4), 256, SMG_TOT>>>(a, a, SB);   // tmp1 = hs @ c1_sp_Wl
    }
    agg_mean2_kernel<<<NSTK + NPOL, 128>>>(pA, off_ps, src_ps, sC, NSTK,
                                           sD, off_sp, src_sp, pC);
    {
        GProb a = prob(sC, w[0], sA, w[1], c1_ps_bl, nullptr, sB, NSTK, 512, 2, 1);
        GProb b = prob(pA, w[3], nullptr, nullptr, c1_sp_bl, pC, pB, NPOL, 512, 1, 1);
        gemm_fp16_dual<<<dim3(SB + PB, 4), 256, SMG_TOT>>>(a, b, SB);
    }

    // ---- layer 2 ----
    {
        GProb a = prob(sB, w[6], nullptr, nullptr, nullptr, nullptr, sD, NSTK, 512, 1, 0);
        gemm_fp16_dual<<<dim3(SB, 4), 256, SMG_TOT>>>(a, a, SB);   // tmp2
    }
    agg_mean2_kernel<<<NSTK + NPOL, 128>>>(pB, off_ps, src_ps, sC, NSTK,
                                           sD, off_sp, src_sp, pC);
    {
        GProb a = prob(sC, w[4], sB, w[5], c2_ps_bl, nullptr, sA, NSTK, 512, 2, 1);
        GProb b = prob(pB, w[7], nullptr, nullptr, c2_sp_bl, pC, pA, NPOL, 512, 1, 1);
        gemm_fp16_dual<<<dim3(SB + PB, 4), 256, SMG_TOT>>>(a, b, SB);
    }

    // ---- decoder factorization (merged) ----
    {
        GProb a = prob(pA, w[8], nullptr, nullptr, nullptr, nullptr, pB, NPOL, 512, 1, 0);
        GProb b = prob(sA, w[9], nullptr, nullptr, nullptr, nullptr, sB, NSTK, 512, 1, 0);
        gemm_fp16_dual<<<dim3(PB + SB, 4), 256, SMG_TOT>>>(a, b, PB);
    }

    // ---- fused per-edge decoder ----
    edge_decode_kernel<<<2048, 256>>>(pB, sB, attr,
                                      d1_W + (size_t)1024 * HID,
                                      d1_W + (size_t)1025 * HID,
                                      d1_b, d2_W, d2_b, trow, tcol, out);
}

// round 13
// speedup vs baseline: 1.0322x; 1.0322x over previous
#include <cuda_runtime.h>
#include <cuda_fp16.h>
#include <mma.h>
#include <cstdint>

using namespace nvcuda;

#define NPOL 20000
#define NSTK 10000
#define EDG  400000
#define HID  512
#define NC   3

// padded row counts (multiples of 128): no bounds checks in GEMM epilogues
#define PROWS 20096
#define SROWS 10112

#define WBIG (512 * 512)
#define WSML (64 * 512)

// ---------------- device scratch (fp16 activation buffers, reused across stages) ----
__device__ __half g_pA[(size_t)PROWS * HID];   // hp0 -> hp2
__device__ __half g_pB[(size_t)PROWS * HID];   // hp1 -> A
__device__ __half g_pC[(size_t)PROWS * HID];   // mean_sp(tmp)
__device__ __half g_sA[(size_t)SROWS * HID];   // hs0 -> hs2
__device__ __half g_sB[(size_t)SROWS * HID];   // hs1 -> B
__device__ __half g_sC[(size_t)SROWS * HID];   // mean_ps
__device__ __half g_sD[(size_t)SROWS * HID];   // tmp (hs @ sp_Wl)

__device__ __half g_w16[10 * WBIG + 2 * WSML];
__device__ __half g_xp16[(size_t)NPOL * 64];
__device__ __half g_xs16[(size_t)NSTK * 64];

__device__ int g_cnt_ps[NSTK];
__device__ int g_off_ps[NSTK + 1];
__device__ int g_cur_ps[NSTK];
__device__ int g_src_ps[EDG];

__device__ int g_cnt_sp[NPOL];
__device__ int g_off_sp[NPOL + 1];
__device__ int g_cur_sp[NPOL];
__device__ int g_src_sp[EDG];

// ---------------- f32 -> f16 converts (weights + raw inputs) ----------------
struct CPack {
    const float* src[14];
    __half*      dst[14];
    int          cnt[14];
};

__global__ __launch_bounds__(256) void convert_all_kernel(CPack p) {
    int s = blockIdx.y;
    const float4* src = reinterpret_cast<const float4*>(p.src[s]);
    __half2* dst = reinterpret_cast<__half2*>(p.dst[s]);
    int n4 = p.cnt[s] >> 2;
    for (int i = blockIdx.x * blockDim.x + threadIdx.x; i < n4; i += gridDim.x * blockDim.x) {
        float4 v = src[i];
        dst[2 * i]     = __floats2half2_rn(v.x, v.y);
        dst[2 * i + 1] = __floats2half2_rn(v.z, v.w);
    }
}

// ---------------- CSR build ----------------
__global__ void zero2_kernel(int* a, int na, int* b, int nb) {
    int i  = blockIdx.x * blockDim.x + threadIdx.x;
    int st = gridDim.x * blockDim.x;
    for (int j = i; j < na; j += st) a[j] = 0;
    for (int j = i; j < nb; j += st) b[j] = 0;
}

__global__ void histo2_kernel(const int* __restrict__ d0, int* c0,
                              const int* __restrict__ d1, int* c1, int n) {
    int i  = blockIdx.x * blockDim.x + threadIdx.x;
    int st = gridDim.x * blockDim.x;
    for (int e = i; e < n; e += st) {
        atomicAdd(&c0[d0[e]], 1);
        atomicAdd(&c1[d1[e]], 1);
    }
}

// warp-shuffle scan: 4 block barriers per 1024-tile
__global__ __launch_bounds__(1024) void exscan2_kernel(
    const int* __restrict__ cnt0, int n0, int* off0, int* cur0,
    const int* __restrict__ cnt1, int n1, int* off1, int* cur1) {
    const int* cnt = blockIdx.x ? cnt1 : cnt0;
    int  n   = blockIdx.x ? n1 : n0;
    int* off = blockIdx.x ? off1 : off0;
    int* cur = blockIdx.x ? cur1 : cur0;

    __shared__ int sWarp[32];
    __shared__ int sTotal;
    __shared__ int sCarry;
    int tid  = threadIdx.x;
    int wid  = tid >> 5;
    int lane = tid & 31;
    if (tid == 0) sCarry = 0;
    __syncthreads();

    for (int base = 0; base < n; base += 1024) {
        int i = base + tid;
        int v = (i < n) ? cnt[i] : 0;
        int incl = v;
        #pragma unroll
        for (int o = 1; o < 32; o <<= 1) {
            int t = __shfl_up_sync(0xffffffffu, incl, o);
            if (lane >= o) incl += t;
        }
        if (lane == 31) sWarp[wid] = incl;
        __syncthreads();
        if (wid == 0) {
            int wv = sWarp[lane];
            int wi = wv;
            #pragma unroll
            for (int o = 1; o < 32; o <<= 1) {
                int t = __shfl_up_sync(0xffffffffu, wi, o);
                if (lane >= o) wi += t;
            }
            sWarp[lane] = wi - wv;
            if (lane == 31) sTotal = wi;
        }
        __syncthreads();
        int carry = sCarry;
        if (i < n) {
            int ex = carry + sWarp[wid] + incl - v;
            off[i] = ex;
            cur[i] = ex;
        }
        __syncthreads();
        if (tid == 0) sCarry = carry + sTotal;
        __syncthreads();
    }
    if (tid == 0) off[n] = sCarry;
}

__global__ void scatter2_kernel(const int* __restrict__ s0, const int* __restrict__ dd0,
                                int* cur0, int* o0,
                                const int* __restrict__ s1, const int* __restrict__ dd1,
                                int* cur1, int* o1, int n) {
    int i  = blockIdx.x * blockDim.x + threadIdx.x;
    int st = gridDim.x * blockDim.x;
    for (int e = i; e < n; e += st) {
        int p0 = atomicAdd(&cur0[dd0[e]], 1);
        o0[p0] = s0[e];
        int p1 = atomicAdd(&cur1[dd1[e]], 1);
        o1[p1] = s1[e];
    }
}

// ---------------- mean aggregation over CSR, merged pair (fp16 in/out, fp32 accum) ----
__global__ __launch_bounds__(128) void agg_mean2_kernel(
    const __half* __restrict__ X0, const int* __restrict__ off0,
    const int* __restrict__ srcs0, __half* __restrict__ out0, int nd0,
    const __half* __restrict__ X1, const int* __restrict__ off1,
    const int* __restrict__ srcs1, __half* __restrict__ out1) {
    const bool first = (int)blockIdx.x < nd0;
    const __half* X  = first ? X0 : X1;
    const int* off   = first ? off0 : off1;
    const int* srcs  = first ? srcs0 : srcs1;
    __half* out      = first ? out0 : out1;
    int d = first ? blockIdx.x : (blockIdx.x - nd0);

    int tid = threadIdx.x;
    int beg = off[d];
    int end = off[d + 1];

    __shared__ int sIdx[128];
    float a0 = 0.f, a1 = 0.f, a2 = 0.f, a3 = 0.f;

    for (int cb = beg; cb < end; cb += 128) {
        int m = min(128, end - cb);
        if (tid < m) sIdx[tid] = srcs[cb + tid];
        __syncthreads();
        int j = 0;
        for (; j + 4 <= m; j += 4) {
            uint2 v0 = reinterpret_cast<const uint2*>(X + (size_t)sIdx[j]     * HID)[tid];
            uint2 v1 = reinterpret_cast<const uint2*>(X + (size_t)sIdx[j + 1] * HID)[tid];
            uint2 v2 = reinterpret_cast<const uint2*>(X + (size_t)sIdx[j + 2] * HID)[tid];
            uint2 v3 = reinterpret_cast<const uint2*>(X + (size_t)sIdx[j + 3] * HID)[tid];
            float2 f;
            f = __half22float2(*reinterpret_cast<__half2*>(&v0.x)); a0 += f.x; a1 += f.y;
            f = __half22float2(*reinterpret_cast<__half2*>(&v0.y)); a2 += f.x; a3 += f.y;
            f = __half22float2(*reinterpret_cast<__half2*>(&v1.x)); a0 += f.x; a1 += f.y;
            f = __half22float2(*reinterpret_cast<__half2*>(&v1.y)); a2 += f.x; a3 += f.y;
            f = __half22float2(*reinterpret_cast<__half2*>(&v2.x)); a0 += f.x; a1 += f.y;
            f = __half22float2(*reinterpret_cast<__half2*>(&v2.y)); a2 += f.x; a3 += f.y;
            f = __half22float2(*reinterpret_cast<__half2*>(&v3.x)); a0 += f.x; a1 += f.y;
            f = __half22float2(*reinterpret_cast<__half2*>(&v3.y)); a2 += f.x; a3 += f.y;
        }
        for (; j < m; j++) {
            uint2 v = reinterpret_cast<const uint2*>(X + (size_t)sIdx[j] * HID)[tid];
            float2 f;
            f = __half22float2(*reinterpret_cast<__half2*>(&v.x)); a0 += f.x; a1 += f.y;
            f = __half22float2(*reinterpret_cast<__half2*>(&v.y)); a2 += f.x; a3 += f.y;
        }
        __syncthreads();
    }
    float inv = (end > beg) ? 1.0f / (float)(end - beg) : 0.0f;
    uint2 ov;
    *reinterpret_cast<__half2*>(&ov.x) = __floats2half2_rn(a0 * inv, a1 * inv);
    *reinterpret_cast<__half2*>(&ov.y) = __floats2half2_rn(a2 * inv, a3 * inv);
    reinterpret_cast<uint2*>(out + (size_t)d * HID)[tid] = ov;
}

// ---------------- cp.async helpers ----------------
__device__ __forceinline__ void cp_async16(void* dst, const void* src, bool pred) {
    uint32_t s = (uint32_t)__cvta_generic_to_shared(dst);
    int n = pred ? 16 : 0;
    asm volatile("cp.async.cg.shared.global [%0], [%1], 16, %2;\n" :: "r"(s), "l"(src), "r"(n));
}
__device__ __forceinline__ void cp_commit() { asm volatile("cp.async.commit_group;\n"); }
template <int N>
__device__ __forceinline__ void cp_wait() { asm volatile("cp.async.wait_group %0;\n" :: "n"(N)); }

// ---------------- fp16 WMMA GEMM (dual-problem), fp16 output — R11 configuration ----
// BM=128, BN=128, BK=32, 256 threads (8 warps; warp tile 32x64 = 2x4 m16n16k16)
// 4-stage cp.async pipeline, one __syncthreads per chunk.
#define XLDH 40
#define WLDH 136
#define SLDF 20
#define SMO_XS    0
#define SMO_WS    40960
#define SMO_BIAS  75776
#define SMO_STAGE 76288
#define SMG_TOT   86528

struct GProb {
    const __half* X0; const __half* W0;
    const __half* X1; const __half* W1;
    const float*  bias; const __half* C0;
    __half* C;
    int M, K, npair, dorelu;
};

__global__ __launch_bounds__(256) void gemm_fp16_dual(GProb pa, GProb pb, int split) {
    extern __shared__ __align__(16) char dsm[];
    __half (*Xs)[128][XLDH] = reinterpret_cast<__half(*)[128][XLDH]>(dsm + SMO_XS);
    __half (*Ws)[32][WLDH]  = reinterpret_cast<__half(*)[32][WLDH]>(dsm + SMO_WS);
    float* s_bias  = reinterpret_cast<float*>(dsm + SMO_BIAS);
    float* s_stage = reinterpret_cast<float*>(dsm + SMO_STAGE);

    const bool  first = (int)blockIdx.x < split;
    const GProb P     = first ? pa : pb;
    const int   bx    = first ? blockIdx.x : (blockIdx.x - split);

    const int row0 = bx * 128;
    const int n0   = blockIdx.y * 128;
    const int tid  = threadIdx.x;
    const int warp = tid >> 5;
    const int lane = tid & 31;
    const int wm   = warp >> 1;   // 0..3
    const int wn   = warp & 1;    // 0..1

    if (tid < 128) s_bias[tid] = P.bias ? P.bias[n0 + tid] : 0.0f;

    wmma::fragment<wmma::accumulator, 16, 16, 16, float> acc[2][4];
    #pragma unroll
    for (int i = 0; i < 2; i++)
        #pragma unroll
        for (int j = 0; j < 4; j++)
            wmma::fill_fragment(acc[i][j], 0.0f);

    const int CK = P.K >> 5;
    const int T  = P.npair * CK;
    const int K  = P.K;
    const int M  = P.M;

    auto load_chunk = [&](int c, int buf) {
        int pair = (c >= CK) ? 1 : 0;
        const __half* X = pair ? P.X1 : P.X0;
        const __half* W = pair ? P.W1 : P.W0;
        int kk = (c - pair * CK) * 32;
        #pragma unroll
        for (int q = 0; q < 2; q++) {
            int u = tid + q * 256;
            int r = u >> 2, cu = u & 3;
            int rg = row0 + r;
            cp_async16(&Xs[buf][r][cu * 8], X + (size_t)rg * K + kk + cu * 8, rg < M);
        }
        #pragma unroll
        for (int q = 0; q < 2; q++) {
            int u = tid + q * 256;
            int r = u >> 4, cu = u & 15;
            cp_async16(&Ws[buf][r][cu * 8], W + (size_t)(kk + r) * HID + n0 + cu * 8, true);
        }
        cp_commit();
    };

    auto compute = [&](int buf) {
        #pragma unroll
        for (int kk = 0; kk < 32; kk += 16) {
            wmma::fragment<wmma::matrix_a, 16, 16, 16, __half, wmma::row_major> a[2];
            wmma::fragment<wmma::matrix_b, 16, 16, 16, __half, wmma::row_major> b[4];
            #pragma unroll
            for (int i = 0; i < 2; i++)
                wmma::load_matrix_sync(a[i], &Xs[buf][wm * 32 + i * 16][kk], XLDH);
            #pragma unroll
            for (int j = 0; j < 4; j++)
                wmma::load_matrix_sync(b[j], &Ws[buf][kk][wn * 64 + j * 16], WLDH);
            #pragma unroll
            for (int i = 0; i < 2; i++)
                #pragma unroll
                for (int j = 0; j < 4; j++)
                    wmma::mma_sync(acc[i][j], a[i], b[j], acc[i][j]);
        }
    };

    // 4-stage pipeline: prefetch up to 3 chunks, one barrier per chunk.
    load_chunk(0, 0);
    if (T > 1) load_chunk(1, 1);
    if (T > 2) load_chunk(2, 2);
    for (int t = 0; t < T; t++) {
        if (t + 2 < T)      cp_wait<2>();
        else if (t + 1 < T) cp_wait<1>();
        else                cp_wait<0>();
        __syncthreads();
        compute(t & 3);
        if (t + 3 < T) load_chunk(t + 3, (t + 3) & 3);
    }

    // epilogue: per-warp 16x16 f32 staging, bias/C0/relu, half8 stores
    float* stw = s_stage + warp * (16 * SLDF);
    const int lr = lane >> 1;
    const int lc = (lane & 1) * 8;
    #pragma unroll
    for (int i = 0; i < 2; i++) {
        #pragma unroll
        for (int j = 0; j < 4; j++) {
            wmma::store_matrix_sync(stw, acc[i][j], SLDF, wmma::mem_row_major);
            __syncwarp();
            int grow = row0 + wm * 32 + i * 16 + lr;
            int bcol = wn * 64 + j * 16 + lc;
            const float* sp = stw + lr * SLDF + lc;
            float v[8];
            #pragma unroll
            for (int t = 0; t < 8; t++) v[t] = sp[t] + s_bias[bcol + t];
            if (P.C0) {
                uint4 cz = *reinterpret_cast<const uint4*>(P.C0 + (size_t)grow * HID + n0 + bcol);
                float2 c0 = __half22float2(*reinterpret_cast<__half2*>(&cz.x));
                float2 c1 = __half22float2(*reinterpret_cast<__half2*>(&cz.y));
                float2 c2 = __half22float2(*reinterpret_cast<__half2*>(&cz.z));
                float2 c3 = __half22float2(*reinterpret_cast<__half2*>(&cz.w));
                v[0] += c0.x; v[1] += c0.y; v[2] += c1.x; v[3] += c1.y;
                v[4] += c2.x; v[5] += c2.y; v[6] += c3.x; v[7] += c3.y;
            }
            if (P.dorelu) {
                #pragma unroll
                for (int t = 0; t < 8; t++) v[t] = fmaxf(v[t], 0.0f);
            }
            uint4 ov;
            *reinterpret_cast<__half2*>(&ov.x) = __floats2half2_rn(v[0], v[1]);
            *reinterpret_cast<__half2*>(&ov.y) = __floats2half2_rn(v[2], v[3]);
            *reinterpret_cast<__half2*>(&ov.z) = __floats2half2_rn(v[4], v[5]);
            *reinterpret_cast<__half2*>(&ov.w) = __floats2half2_rn(v[6], v[7]);
            *reinterpret_cast<uint4*>(P.C + (size_t)grow * HID + n0 + bcol) = ov;
            __syncwarp();
        }
    }
}

// ---------------- fused per-edge decoder (fp16 A/B via uint4, fp32 math) ----------------
__global__ __launch_bounds__(256) void edge_decode_kernel(
    const __half* __restrict__ Aa, const __half* __restrict__ Bb,
    const float* __restrict__ attr,
    const float* __restrict__ w0, const float* __restrict__ w1,
    const float* __restrict__ b1,
    const float* __restrict__ d2W, const float* __restrict__ d2b,
    const int* __restrict__ erow, const int* __restrict__ ecol,
    float* __restrict__ out) {
    __shared__ float s_w0[512], s_w1[512], s_b[512], s_d0[512], s_d1[512], s_d2[512];
    int tid = threadIdx.x;
    for (int i = tid; i < HID; i += 256) {
        s_w0[i] = w0[i];
        s_w1[i] = w1[i];
        s_b[i]  = b1[i];
        s_d0[i] = d2W[i * 3 + 0];
        s_d1[i] = d2W[i * 3 + 1];
        s_d2[i] = d2W[i * 3 + 2];
    }
    __syncthreads();
    float db0 = d2b[0], db1 = d2b[1], db2 = d2b[2];
    int lane = tid & 31;
    int warp = tid >> 5;

    for (int e = blockIdx.x * 8 + warp; e < EDG; e += gridDim.x * 8) {
        int r = erow[e];
        int c = ecol[e];
        float a0 = attr[2 * e];
        float a1 = attr[2 * e + 1];
        const uint4* A4 = reinterpret_cast<const uint4*>(Aa + (size_t)r * HID);
        const uint4* B4 = reinterpret_cast<const uint4*>(Bb + (size_t)c * HID);
        float s0 = 0.f, s1 = 0.f, s2 = 0.f;
        #pragma unroll
        for (int k = 0; k < 2; k++) {
            int q = k * 32 + lane;          // uint4 index: 8 halves per lane
            uint4 au = A4[q], bu = B4[q];
            int base = q * 8;
            const uint32_t* ap = reinterpret_cast<const uint32_t*>(&au);
            const uint32_t* bp = reinterpret_cast<const uint32_t*>(&bu);
            #pragma unroll
            for (int h2 = 0; h2 < 4; h2++) {
                float2 fa = __half22float2(*reinterpret_cast<const __half2*>(&ap[h2]));
                float2 fb = __half22float2(*reinterpret_cast<const __half2*>(&bp[h2]));
                int i0 = base + h2 * 2;
                float hv;
                hv = fmaxf(fa.x + fb.x + a0 * s_w0[i0] + a1 * s_w1[i0] + s_b[i0], 0.f);
                s0 += hv * s_d0[i0]; s1 += hv * s_d1[i0]; s2 += hv * s_d2[i0];
                hv = fmaxf(fa.y + fb.y + a0 * s_w0[i0 + 1] + a1 * s_w1[i0 + 1] + s_b[i0 + 1], 0.f);
                s0 += hv * s_d0[i0 + 1]; s1 += hv * s_d1[i0 + 1]; s2 += hv * s_d2[i0 + 1];
            }
        }
        #pragma unroll
        for (int o = 16; o > 0; o >>= 1) {
            s0 += __shfl_xor_sync(0xffffffffu, s0, o);
            s1 += __shfl_xor_sync(0xffffffffu, s1, o);
            s2 += __shfl_xor_sync(0xffffffffu, s2, o);
        }
        if (lane == 0) {
            out[(size_t)e * 3 + 0] = s0 + db0;
            out[(size_t)e * 3 + 1] = s1 + db1;
            out[(size_t)e * 3 + 2] = s2 + db2;
        }
    }
}

// ---------------- host launch ----------------
extern "C" void kernel_launch(void* const* d_in, const int* in_sizes, int n_in,
                              void* d_out, int out_size) {
    (void)in_sizes; (void)n_in; (void)out_size;

    const float* x_pol = (const float*)d_in[0];
    const float* x_stk = (const float*)d_in[1];
    const float* attr  = (const float*)d_in[2];
    const float* Wp    = (const float*)d_in[3];
    const float* bp    = (const float*)d_in[4];
    const float* Ws    = (const float*)d_in[5];
    const float* bs    = (const float*)d_in[6];
    const float* c1_ps_Wl = (const float*)d_in[7];
    const float* c1_ps_bl = (const float*)d_in[8];
    const float* c1_ps_Wr = (const float*)d_in[9];
    const float* c1_sp_Wl = (const float*)d_in[10];
    const float* c1_sp_bl = (const float*)d_in[11];
    const float* c1_sp_Wr = (const float*)d_in[12];
    const float* c2_ps_Wl = (const float*)d_in[13];
    const float* c2_ps_bl = (const float*)d_in[14];
    const float* c2_ps_Wr = (const float*)d_in[15];
    const float* c2_sp_Wl = (const float*)d_in[16];
    const float* c2_sp_bl = (const float*)d_in[17];
    const float* c2_sp_Wr = (const float*)d_in[18];
    const float* d1_W  = (const float*)d_in[19];   // [1026, 512]
    const float* d1_b  = (const float*)d_in[20];
    const float* d2_W  = (const float*)d_in[21];   // [512, 3]
    const float* d2_b  = (const float*)d_in[22];
    const int* eps_src = (const int*)d_in[23];
    const int* eps_dst = (const int*)d_in[24];
    const int* esp_src = (const int*)d_in[25];
    const int* esp_dst = (const int*)d_in[26];
    const int* trow    = (const int*)d_in[27];
    const int* tcol    = (const int*)d_in[28];
    float* out = (float*)d_out;

    void* p;
    cudaGetSymbolAddress(&p, g_pA);     __half* pA = (__half*)p;
    cudaGetSymbolAddress(&p, g_pB);     __half* pB = (__half*)p;
    cudaGetSymbolAddress(&p, g_pC);     __half* pC = (__half*)p;
    cudaGetSymbolAddress(&p, g_sA);     __half* sA = (__half*)p;
    cudaGetSymbolAddress(&p, g_sB);     __half* sB = (__half*)p;
    cudaGetSymbolAddress(&p, g_sC);     __half* sC = (__half*)p;
    cudaGetSymbolAddress(&p, g_sD);     __half* sD = (__half*)p;
    cudaGetSymbolAddress(&p, g_w16);    __half* w16 = (__half*)p;
    cudaGetSymbolAddress(&p, g_xp16);   __half* xp16 = (__half*)p;
    cudaGetSymbolAddress(&p, g_xs16);   __half* xs16 = (__half*)p;
    cudaGetSymbolAddress(&p, g_cnt_ps); int* cnt_ps = (int*)p;
    cudaGetSymbolAddress(&p, g_off_ps); int* off_ps = (int*)p;
    cudaGetSymbolAddress(&p, g_cur_ps); int* cur_ps = (int*)p;
    cudaGetSymbolAddress(&p, g_src_ps); int* src_ps = (int*)p;
    cudaGetSymbolAddress(&p, g_cnt_sp); int* cnt_sp = (int*)p;
    cudaGetSymbolAddress(&p, g_off_sp); int* off_sp = (int*)p;
    cudaGetSymbolAddress(&p, g_cur_sp); int* cur_sp = (int*)p;
    cudaGetSymbolAddress(&p, g_src_sp); int* src_sp = (int*)p;

    cudaFuncSetAttribute(gemm_fp16_dual, cudaFuncAttributeMaxDynamicSharedMemorySize, SMG_TOT);

    // fp16 weight table
    __half* w[12];
    const float* wsrc[12] = {c1_ps_Wl, c1_ps_Wr, c1_sp_Wl, c1_sp_Wr,
                             c2_ps_Wl, c2_ps_Wr, c2_sp_Wl, c2_sp_Wr,
                             d1_W, d1_W + (size_t)512 * HID, Wp, Ws};
    for (int i = 0; i < 10; i++) w[i] = w16 + (size_t)i * WBIG;
    w[10] = w16 + (size_t)10 * WBIG;
    w[11] = w16 + (size_t)10 * WBIG + WSML;

    CPack cp;
    for (int i = 0; i < 12; i++) { cp.src[i] = wsrc[i]; cp.dst[i] = w[i]; cp.cnt[i] = (i < 10) ? WBIG : WSML; }
    cp.src[12] = x_pol; cp.dst[12] = xp16; cp.cnt[12] = NPOL * 64;
    cp.src[13] = x_stk; cp.dst[13] = xs16; cp.cnt[13] = NSTK * 64;

    const int PB = PROWS / 128;   // 157
    const int SB = SROWS / 128;   // 79

    auto prob = [](const __half* X0, const __half* W0, const __half* X1, const __half* W1,
                   const float* bias, const __half* C0, __half* C,
                   int M, int K, int npair, int dorelu) {
        GProb g; g.X0 = X0; g.W0 = W0; g.X1 = X1; g.W1 = W1;
        g.bias = bias; g.C0 = C0; g.C = C; g.M = M; g.K = K; g.npair = npair; g.dorelu = dorelu;
        return g;
    };

    // converts + CSR front
    convert_all_kernel<<<dim3(256, 14), 256>>>(cp);
    zero2_kernel<<<64, 256>>>(cnt_ps, NSTK, cnt_sp, NPOL);
    histo2_kernel<<<400, 256>>>(eps_dst, cnt_ps, esp_dst, cnt_sp, EDG);

    // projections (merged) — launch slot 4 for ncu
    {
        GProb a = prob(xp16, w[10], nullptr, nullptr, bp, nullptr, pA, NPOL, 64, 1, 1);
        GProb b = prob(xs16, w[11], nullptr, nullptr, bs, nullptr, sA, NSTK, 64, 1, 1);
        gemm_fp16_dual<<<dim3(PB + SB, 4), 256, SMG_TOT>>>(a, b, PB);
    }

    // finish CSR
    exscan2_kernel<<<2, 1024>>>(cnt_ps, NSTK, off_ps, cur_ps, cnt_sp, NPOL, off_sp, cur_sp);
    scatter2_kernel<<<400, 256>>>(eps_src, eps_dst, cur_ps, src_ps,
                                  esp_src, esp_dst, cur_sp, src_sp, EDG);

    // ---- layer 1 ----
    {
        GProb a = prob(sA, w[2], nullptr, nullptr, nullptr, nullptr, sD, NSTK, 512, 1, 0);
        gemm_fp16_dual<<<dim3(SB, 4), 256, SMG_TOT>>>(a, a, SB);   // tmp1 = hs @ c1_sp_Wl
    }
    agg_mean2_kernel<<<NSTK + NPOL, 128>>>(pA, off_ps, src_ps, sC, NSTK,
                                           sD, off_sp, src_sp, pC);
    {
        GProb a = prob(sC, w[0], sA, w[1], c1_ps_bl, nullptr, sB, NSTK, 512, 2, 1);
        GProb b = prob(pA, w[3], nullptr, nullptr, c1_sp_bl, pC, pB, NPOL, 512, 1, 1);
        gemm_fp16_dual<<<dim3(SB + PB, 4), 256, SMG_TOT>>>(a, b, SB);
    }

    // ---- layer 2 ----
    {
        GProb a = prob(sB, w[6], nullptr, nullptr, nullptr, nullptr, sD, NSTK, 512, 1, 0);
        gemm_fp16_dual<<<dim3(SB, 4), 256, SMG_TOT>>>(a, a, SB);   // tmp2
    }
    agg_mean2_kernel<<<NSTK + NPOL, 128>>>(pB, off_ps, src_ps, sC, NSTK,
                                           sD, off_sp, src_sp, pC);
    {
        GProb a = prob(sC, w[4], sB, w[5], c2_ps_bl, nullptr, sA, NSTK, 512, 2, 1);
        GProb b = prob(pB, w[7], nullptr, nullptr, c2_sp_bl, pC, pA, NPOL, 512, 1, 1);
        gemm_fp16_dual<<<dim3(SB + PB, 4), 256, SMG_TOT>>>(a, b, SB);
    }

    // ---- decoder factorization (merged) ----
    {
        GProb a = prob(pA, w[8], nullptr, nullptr, nullptr, nullptr, pB, NPOL, 512, 1, 0);
        GProb b = prob(sA, w[9], nullptr, nullptr, nullptr, nullptr, sB, NSTK, 512, 1, 0);
        gemm_fp16_dual<<<dim3(PB + SB, 4), 256, SMG_TOT>>>(a, b, PB);
    }

    // ---- fused per-edge decoder ----
    edge_decode_kernel<<<2048, 256>>>(pB, sB, attr,
                                      d1_W + (size_t)1024 * HID,
                                      d1_W + (size_t)1025 * HID,
                                      d1_b, d2_W, d2_b, trow, tcol, out);
}

// round 15
// speedup vs baseline: 1.0715x; 1.0381x over previous
#include <cuda_runtime.h>
#include <cuda_fp16.h>
#include <mma.h>
#include <cstdint>

using namespace nvcuda;

#define NPOL 20000
#define NSTK 10000
#define EDG  400000
#define HID  512
#define NC   3

#define PROWS 20096
#define SROWS 10112

#define WBIG (512 * 512)
#define WSML (64 * 512)

// ---------------- device scratch ----------------
__device__ __half g_pA[(size_t)PROWS * HID];
__device__ __half g_pB[(size_t)PROWS * HID];
__device__ __half g_pC[(size_t)PROWS * HID];
__device__ __half g_sA[(size_t)SROWS * HID];
__device__ __half g_sB[(size_t)SROWS * HID];
__device__ __half g_sC[(size_t)SROWS * HID];
__device__ __half g_sD[(size_t)SROWS * HID];

__device__ __half g_w16[10 * WBIG + 2 * WSML];
__device__ __half g_xp16[(size_t)NPOL * 64];
__device__ __half g_xs16[(size_t)NSTK * 64];

__device__ int g_cnt_ps[NSTK];
__device__ int g_off_ps[NSTK + 1];
__device__ int g_cur_ps[NSTK];
__device__ int g_src_ps[EDG];

__device__ int g_cnt_sp[NPOL];
__device__ int g_off_sp[NPOL + 1];
__device__ int g_cur_sp[NPOL];
__device__ int g_src_sp[EDG];

// ---------------- f32 -> f16 converts ----------------
struct CPack {
    const float* src[14];
    __half*      dst[14];
    int          cnt[14];
};

__global__ __launch_bounds__(256) void convert_all_kernel(CPack p) {
    int s = blockIdx.y;
    const float4* src = reinterpret_cast<const float4*>(p.src[s]);
    __half2* dst = reinterpret_cast<__half2*>(p.dst[s]);
    int n4 = p.cnt[s] >> 2;
    for (int i = blockIdx.x * blockDim.x + threadIdx.x; i < n4; i += gridDim.x * blockDim.x) {
        float4 v = src[i];
        dst[2 * i]     = __floats2half2_rn(v.x, v.y);
        dst[2 * i + 1] = __floats2half2_rn(v.z, v.w);
    }
}

// ---------------- CSR build ----------------
__global__ void zero2_kernel(int* a, int na, int* b, int nb) {
    int i  = blockIdx.x * blockDim.x + threadIdx.x;
    int st = gridDim.x * blockDim.x;
    for (int j = i; j < na; j += st) a[j] = 0;
    for (int j = i; j < nb; j += st) b[j] = 0;
}

__global__ void histo2_kernel(const int* __restrict__ d0, int* c0,
                              const int* __restrict__ d1, int* c1, int n) {
    int i  = blockIdx.x * blockDim.x + threadIdx.x;
    int st = gridDim.x * blockDim.x;
    for (int e = i; e < n; e += st) {
        atomicAdd(&c0[d0[e]], 1);
        atomicAdd(&c1[d1[e]], 1);
    }
}

__global__ __launch_bounds__(1024) void exscan2_kernel(
    const int* __restrict__ cnt0, int n0, int* off0, int* cur0,
    const int* __restrict__ cnt1, int n1, int* off1, int* cur1) {
    const int* cnt = blockIdx.x ? cnt1 : cnt0;
    int  n   = blockIdx.x ? n1 : n0;
    int* off = blockIdx.x ? off1 : off0;
    int* cur = blockIdx.x ? cur1 : cur0;

    __shared__ int sWarp[32];
    __shared__ int sTotal;
    __shared__ int sCarry;
    int tid  = threadIdx.x;
    int wid  = tid >> 5;
    int lane = tid & 31;
    if (tid == 0) sCarry = 0;
    __syncthreads();

    for (int base = 0; base < n; base += 1024) {
        int i = base + tid;
        int v = (i < n) ? cnt[i] : 0;
        int incl = v;
        #pragma unroll
        for (int o = 1; o < 32; o <<= 1) {
            int t = __shfl_up_sync(0xffffffffu, incl, o);
            if (lane >= o) incl += t;
        }
        if (lane == 31) sWarp[wid] = incl;
        __syncthreads();
        if (wid == 0) {
            int wv = sWarp[lane];
            int wi = wv;
            #pragma unroll
            for (int o = 1; o < 32; o <<= 1) {
                int t = __shfl_up_sync(0xffffffffu, wi, o);
                if (lane >= o) wi += t;
            }
            sWarp[lane] = wi - wv;
            if (lane == 31) sTotal = wi;
        }
        __syncthreads();
        int carry = sCarry;
        if (i < n) {
            int ex = carry + sWarp[wid] + incl - v;
            off[i] = ex;
            cur[i] = ex;
        }
        __syncthreads();
        if (tid == 0) sCarry = carry + sTotal;
        __syncthreads();
    }
    if (tid == 0) off[n] = sCarry;
}

__global__ void scatter2_kernel(const int* __restrict__ s0, const int* __restrict__ dd0,
                                int* cur0, int* o0,
                                const int* __restrict__ s1, const int* __restrict__ dd1,
                                int* cur1, int* o1, int n) {
    int i  = blockIdx.x * blockDim.x + threadIdx.x;
    int st = gridDim.x * blockDim.x;
    for (int e = i; e < n; e += st) {
        int p0 = atomicAdd(&cur0[dd0[e]], 1);
        o0[p0] = s0[e];
        int p1 = atomicAdd(&cur1[dd1[e]], 1);
        o1[p1] = s1[e];
    }
}

// ---------------- mean aggregation over CSR (single problem) ----------------
__global__ __launch_bounds__(128) void agg_mean_kernel(
    const __half* __restrict__ X, const int* __restrict__ off,
    const int* __restrict__ srcs, __half* __restrict__ out) {
    int d   = blockIdx.x;
    int tid = threadIdx.x;
    int beg = off[d];
    int end = off[d + 1];

    __shared__ int sIdx[128];
    float a0 = 0.f, a1 = 0.f, a2 = 0.f, a3 = 0.f;

    for (int cb = beg; cb < end; cb += 128) {
        int m = min(128, end - cb);
        if (tid < m) sIdx[tid] = srcs[cb + tid];
        __syncthreads();
        int j = 0;
        for (; j + 4 <= m; j += 4) {
            uint2 v0 = reinterpret_cast<const uint2*>(X + (size_t)sIdx[j]     * HID)[tid];
            uint2 v1 = reinterpret_cast<const uint2*>(X + (size_t)sIdx[j + 1] * HID)[tid];
            uint2 v2 = reinterpret_cast<const uint2*>(X + (size_t)sIdx[j + 2] * HID)[tid];
            uint2 v3 = reinterpret_cast<const uint2*>(X + (size_t)sIdx[j + 3] * HID)[tid];
            float2 f;
            f = __half22float2(*reinterpret_cast<__half2*>(&v0.x)); a0 += f.x; a1 += f.y;
            f = __half22float2(*reinterpret_cast<__half2*>(&v0.y)); a2 += f.x; a3 += f.y;
            f = __half22float2(*reinterpret_cast<__half2*>(&v1.x)); a0 += f.x; a1 += f.y;
            f = __half22float2(*reinterpret_cast<__half2*>(&v1.y)); a2 += f.x; a3 += f.y;
            f = __half22float2(*reinterpret_cast<__half2*>(&v2.x)); a0 += f.x; a1 += f.y;
            f = __half22float2(*reinterpret_cast<__half2*>(&v2.y)); a2 += f.x; a3 += f.y;
            f = __half22float2(*reinterpret_cast<__half2*>(&v3.x)); a0 += f.x; a1 += f.y;
            f = __half22float2(*reinterpret_cast<__half2*>(&v3.y)); a2 += f.x; a3 += f.y;
        }
        for (; j < m; j++) {
            uint2 v = reinterpret_cast<const uint2*>(X + (size_t)sIdx[j] * HID)[tid];
            float2 f;
            f = __half22float2(*reinterpret_cast<__half2*>(&v.x)); a0 += f.x; a1 += f.y;
            f = __half22float2(*reinterpret_cast<__half2*>(&v.y)); a2 += f.x; a3 += f.y;
        }
        __syncthreads();
    }
    float inv = (end > beg) ? 1.0f / (float)(end - beg) : 0.0f;
    uint2 ov;
    *reinterpret_cast<__half2*>(&ov.x) = __floats2half2_rn(a0 * inv, a1 * inv);
    *reinterpret_cast<__half2*>(&ov.y) = __floats2half2_rn(a2 * inv, a3 * inv);
    reinterpret_cast<uint2*>(out + (size_t)d * HID)[tid] = ov;
}

// ---------------- cp.async helpers ----------------
__device__ __forceinline__ void cp_async16(void* dst, const void* src, bool pred) {
    uint32_t s = (uint32_t)__cvta_generic_to_shared(dst);
    int n = pred ? 16 : 0;
    asm volatile("cp.async.cg.shared.global [%0], [%1], 16, %2;\n" :: "r"(s), "l"(src), "r"(n));
}
__device__ __forceinline__ void cp_commit() { asm volatile("cp.async.commit_group;\n"); }
template <int N>
__device__ __forceinline__ void cp_wait() { asm volatile("cp.async.wait_group %0;\n" :: "n"(N)); }

// ---------------- fp16 WMMA GEMM (dual-problem), fp16 output — frozen R11 config ----
#define XLDH 40
#define WLDH 136
#define SLDF 20
#define SMO_XS    0
#define SMO_WS    40960
#define SMO_BIAS  75776
#define SMO_STAGE 76288
#define SMG_TOT   86528

struct GProb {
    const __half* X0; const __half* W0;
    const __half* X1; const __half* W1;
    const float*  bias; const __half* C0;
    __half* C;
    int M, K, npair, dorelu;
};

__global__ __launch_bounds__(256) void gemm_fp16_dual(GProb pa, GProb pb, int split) {
    extern __shared__ __align__(16) char dsm[];
    __half (*Xs)[128][XLDH] = reinterpret_cast<__half(*)[128][XLDH]>(dsm + SMO_XS);
    __half (*Ws)[32][WLDH]  = reinterpret_cast<__half(*)[32][WLDH]>(dsm + SMO_WS);
    float* s_bias  = reinterpret_cast<float*>(dsm + SMO_BIAS);
    float* s_stage = reinterpret_cast<float*>(dsm + SMO_STAGE);

    const bool  first = (int)blockIdx.x < split;
    const GProb P     = first ? pa : pb;
    const int   bx    = first ? blockIdx.x : (blockIdx.x - split);

    const int row0 = bx * 128;
    const int n0   = blockIdx.y * 128;
    const int tid  = threadIdx.x;
    const int warp = tid >> 5;
    const int lane = tid & 31;
    const int wm   = warp >> 1;
    const int wn   = warp & 1;

    if (tid < 128) s_bias[tid] = P.bias ? P.bias[n0 + tid] : 0.0f;

    wmma::fragment<wmma::accumulator, 16, 16, 16, float> acc[2][4];
    #pragma unroll
    for (int i = 0; i < 2; i++)
        #pragma unroll
        for (int j = 0; j < 4; j++)
            wmma::fill_fragment(acc[i][j], 0.0f);

    const int CK = P.K >> 5;
    const int T  = P.npair * CK;
    const int K  = P.K;
    const int M  = P.M;

    auto load_chunk = [&](int c, int buf) {
        int pair = (c >= CK) ? 1 : 0;
        const __half* X = pair ? P.X1 : P.X0;
        const __half* W = pair ? P.W1 : P.W0;
        int kk = (c - pair * CK) * 32;
        #pragma unroll
        for (int q = 0; q < 2; q++) {
            int u = tid + q * 256;
            int r = u >> 2, cu = u & 3;
            int rg = row0 + r;
            cp_async16(&Xs[buf][r][cu * 8], X + (size_t)rg * K + kk + cu * 8, rg < M);
        }
        #pragma unroll
        for (int q = 0; q < 2; q++) {
            int u = tid + q * 256;
            int r = u >> 4, cu = u & 15;
            cp_async16(&Ws[buf][r][cu * 8], W + (size_t)(kk + r) * HID + n0 + cu * 8, true);
        }
        cp_commit();
    };

    auto compute = [&](int buf) {
        #pragma unroll
        for (int kk = 0; kk < 32; kk += 16) {
            wmma::fragment<wmma::matrix_a, 16, 16, 16, __half, wmma::row_major> a[2];
            wmma::fragment<wmma::matrix_b, 16, 16, 16, __half, wmma::row_major> b[4];
            #pragma unroll
            for (int i = 0; i < 2; i++)
                wmma::load_matrix_sync(a[i], &Xs[buf][wm * 32 + i * 16][kk], XLDH);
            #pragma unroll
            for (int j = 0; j < 4; j++)
                wmma::load_matrix_sync(b[j], &Ws[buf][kk][wn * 64 + j * 16], WLDH);
            #pragma unroll
            for (int i = 0; i < 2; i++)
                #pragma unroll
                for (int j = 0; j < 4; j++)
                    wmma::mma_sync(acc[i][j], a[i], b[j], acc[i][j]);
        }
    };

    load_chunk(0, 0);
    if (T > 1) load_chunk(1, 1);
    if (T > 2) load_chunk(2, 2);
    for (int t = 0; t < T; t++) {
        if (t + 2 < T)      cp_wait<2>();
        else if (t + 1 < T) cp_wait<1>();
        else                cp_wait<0>();
        __syncthreads();
        compute(t & 3);
        if (t + 3 < T) load_chunk(t + 3, (t + 3) & 3);
    }

    float* stw = s_stage + warp * (16 * SLDF);
    const int lr = lane >> 1;
    const int lc = (lane & 1) * 8;
    #pragma unroll
    for (int i = 0; i < 2; i++) {
        #pragma unroll
        for (int j = 0; j < 4; j++) {
            wmma::store_matrix_sync(stw, acc[i][j], SLDF, wmma::mem_row_major);
            __syncwarp();
            int grow = row0 + wm * 32 + i * 16 + lr;
            int bcol = wn * 64 + j * 16 + lc;
            const float* sp = stw + lr * SLDF + lc;
            float v[8];
            #pragma unroll
            for (int t = 0; t < 8; t++) v[t] = sp[t] + s_bias[bcol + t];
            if (P.C0) {
                uint4 cz = *reinterpret_cast<const uint4*>(P.C0 + (size_t)grow * HID + n0 + bcol);
                float2 c0 = __half22float2(*reinterpret_cast<__half2*>(&cz.x));
                float2 c1 = __half22float2(*reinterpret_cast<__half2*>(&cz.y));
                float2 c2 = __half22float2(*reinterpret_cast<__half2*>(&cz.z));
                float2 c3 = __half22float2(*reinterpret_cast<__half2*>(&cz.w));
                v[0] += c0.x; v[1] += c0.y; v[2] += c1.x; v[3] += c1.y;
                v[4] += c2.x; v[5] += c2.y; v[6] += c3.x; v[7] += c3.y;
            }
            if (P.dorelu) {
                #pragma unroll
                for (int t = 0; t < 8; t++) v[t] = fmaxf(v[t], 0.0f);
            }
            uint4 ov;
            *reinterpret_cast<__half2*>(&ov.x) = __floats2half2_rn(v[0], v[1]);
            *reinterpret_cast<__half2*>(&ov.y) = __floats2half2_rn(v[2], v[3]);
            *reinterpret_cast<__half2*>(&ov.z) = __floats2half2_rn(v[4], v[5]);
            *reinterpret_cast<__half2*>(&ov.w) = __floats2half2_rn(v[6], v[7]);
            *reinterpret_cast<uint4*>(P.C + (size_t)grow * HID + n0 + bcol) = ov;
            __syncwarp();
        }
    }
}

// ---------------- fused per-edge decoder (fp16 A/B via uint4, fp32 math) ----------------
__global__ __launch_bounds__(256) void edge_decode_kernel(
    const __half* __restrict__ Aa, const __half* __restrict__ Bb,
    const float* __restrict__ attr,
    const float* __restrict__ w0, const float* __restrict__ w1,
    const float* __restrict__ b1,
    const float* __restrict__ d2W, const float* __restrict__ d2b,
    const int* __restrict__ erow, const int* __restrict__ ecol,
    float* __restrict__ out) {
    __shared__ float s_w0[512], s_w1[512], s_b[512], s_d0[512], s_d1[512], s_d2[512];
    int tid = threadIdx.x;
    for (int i = tid; i < HID; i += 256) {
        s_w0[i] = w0[i];
        s_w1[i] = w1[i];
        s_b[i]  = b1[i];
        s_d0[i] = d2W[i * 3 + 0];
        s_d1[i] = d2W[i * 3 + 1];
        s_d2[i] = d2W[i * 3 + 2];
    }
    __syncthreads();
    float db0 = d2b[0], db1 = d2b[1], db2 = d2b[2];
    int lane = tid & 31;
    int warp = tid >> 5;

    for (int e = blockIdx.x * 8 + warp; e < EDG; e += gridDim.x * 8) {
        int r = erow[e];
        int c = ecol[e];
        float a0 = attr[2 * e];
        float a1 = attr[2 * e + 1];
        const uint4* A4 = reinterpret_cast<const uint4*>(Aa + (size_t)r * HID);
        const uint4* B4 = reinterpret_cast<const uint4*>(Bb + (size_t)c * HID);
        float s0 = 0.f, s1 = 0.f, s2 = 0.f;
        #pragma unroll
        for (int k = 0; k < 2; k++) {
            int q = k * 32 + lane;
            uint4 au = A4[q], bu = B4[q];
            int base = q * 8;
            const uint32_t* ap = reinterpret_cast<const uint32_t*>(&au);
            const uint32_t* bp = reinterpret_cast<const uint32_t*>(&bu);
            #pragma unroll
            for (int h2 = 0; h2 < 4; h2++) {
                float2 fa = __half22float2(*reinterpret_cast<const __half2*>(&ap[h2]));
                float2 fb = __half22float2(*reinterpret_cast<const __half2*>(&bp[h2]));
                int i0 = base + h2 * 2;
                float hv;
                hv = fmaxf(fa.x + fb.x + a0 * s_w0[i0] + a1 * s_w1[i0] + s_b[i0], 0.f);
                s0 += hv * s_d0[i0]; s1 += hv * s_d1[i0]; s2 += hv * s_d2[i0];
                hv = fmaxf(fa.y + fb.y + a0 * s_w0[i0 + 1] + a1 * s_w1[i0 + 1] + s_b[i0 + 1], 0.f);
                s0 += hv * s_d0[i0 + 1]; s1 += hv * s_d1[i0 + 1]; s2 += hv * s_d2[i0 + 1];
            }
        }
        #pragma unroll
        for (int o = 16; o > 0; o >>= 1) {
            s0 += __shfl_xor_sync(0xffffffffu, s0, o);
            s1 += __shfl_xor_sync(0xffffffffu, s1, o);
            s2 += __shfl_xor_sync(0xffffffffu, s2, o);
        }
        if (lane == 0) {
            out[(size_t)e * 3 + 0] = s0 + db0;
            out[(size_t)e * 3 + 1] = s1 + db1;
            out[(size_t)e * 3 + 2] = s2 + db2;
        }
    }
}

// ---------------- host launch ----------------
extern "C" void kernel_launch(void* const* d_in, const int* in_sizes, int n_in,
                              void* d_out, int out_size) {
    (void)in_sizes; (void)n_in; (void)out_size;

    const float* x_pol = (const float*)d_in[0];
    const float* x_stk = (const float*)d_in[1];
    const float* attr  = (const float*)d_in[2];
    const float* Wp    = (const float*)d_in[3];
    const float* bp    = (const float*)d_in[4];
    const float* Ws    = (const float*)d_in[5];
    const float* bs    = (const float*)d_in[6];
    const float* c1_ps_Wl = (const float*)d_in[7];
    const float* c1_ps_bl = (const float*)d_in[8];
    const float* c1_ps_Wr = (const float*)d_in[9];
    const float* c1_sp_Wl = (const float*)d_in[10];
    const float* c1_sp_bl = (const float*)d_in[11];
    const float* c1_sp_Wr = (const float*)d_in[12];
    const float* c2_ps_Wl = (const float*)d_in[13];
    const float* c2_ps_bl = (const float*)d_in[14];
    const float* c2_ps_Wr = (const float*)d_in[15];
    const float* c2_sp_Wl = (const float*)d_in[16];
    const float* c2_sp_bl = (const float*)d_in[17];
    const float* c2_sp_Wr = (const float*)d_in[18];
    const float* d1_W  = (const float*)d_in[19];
    const float* d1_b  = (const float*)d_in[20];
    const float* d2_W  = (const float*)d_in[21];
    const float* d2_b  = (const float*)d_in[22];
    const int* eps_src = (const int*)d_in[23];
    const int* eps_dst = (const int*)d_in[24];
    const int* esp_src = (const int*)d_in[25];
    const int* esp_dst = (const int*)d_in[26];
    const int* trow    = (const int*)d_in[27];
    const int* tcol    = (const int*)d_in[28];
    float* out = (float*)d_out;

    void* p;
    cudaGetSymbolAddress(&p, g_pA);     __half* pA = (__half*)p;
    cudaGetSymbolAddress(&p, g_pB);     __half* pB = (__half*)p;
    cudaGetSymbolAddress(&p, g_pC);     __half* pC = (__half*)p;
    cudaGetSymbolAddress(&p, g_sA);     __half* sA = (__half*)p;
    cudaGetSymbolAddress(&p, g_sB);     __half* sB = (__half*)p;
    cudaGetSymbolAddress(&p, g_sC);     __half* sC = (__half*)p;
    cudaGetSymbolAddress(&p, g_sD);     __half* sD = (__half*)p;
    cudaGetSymbolAddress(&p, g_w16);    __half* w16 = (__half*)p;
    cudaGetSymbolAddress(&p, g_xp16);   __half* xp16 = (__half*)p;
    cudaGetSymbolAddress(&p, g_xs16);   __half* xs16 = (__half*)p;
    cudaGetSymbolAddress(&p, g_cnt_ps); int* cnt_ps = (int*)p;
    cudaGetSymbolAddress(&p, g_off_ps); int* off_ps = (int*)p;
    cudaGetSymbolAddress(&p, g_cur_ps); int* cur_ps = (int*)p;
    cudaGetSymbolAddress(&p, g_src_ps); int* src_ps = (int*)p;
    cudaGetSymbolAddress(&p, g_cnt_sp); int* cnt_sp = (int*)p;
    cudaGetSymbolAddress(&p, g_off_sp); int* off_sp = (int*)p;
    cudaGetSymbolAddress(&p, g_cur_sp); int* cur_sp = (int*)p;
    cudaGetSymbolAddress(&p, g_src_sp); int* src_sp = (int*)p;

    cudaFuncSetAttribute(gemm_fp16_dual, cudaFuncAttributeMaxDynamicSharedMemorySize, SMG_TOT);

    // side stream + events: created once, outside graph capture (first call is
    // the uncaptured correctness run). Fall back to single-stream if unavailable.
    static cudaStream_t s2 = nullptr;
    static cudaEvent_t ev[6];
    static bool tried = false, use2 = false;
    if (!tried) {
        tried = true;
        if (cudaStreamCreateWithFlags(&s2, cudaStreamNonBlocking) == cudaSuccess) {
            use2 = true;
            for (int i = 0; i < 6; i++) {
                if (cudaEventCreateWithFlags(&ev[i], cudaEventDisableTiming) != cudaSuccess) {
                    use2 = false;
                    break;
                }
            }
        }
    }

    __half* w[12];
    const float* wsrc[12] = {c1_ps_Wl, c1_ps_Wr, c1_sp_Wl, c1_sp_Wr,
                             c2_ps_Wl, c2_ps_Wr, c2_sp_Wl, c2_sp_Wr,
                             d1_W, d1_W + (size_t)512 * HID, Wp, Ws};
    for (int i = 0; i < 10; i++) w[i] = w16 + (size_t)i * WBIG;
    w[10] = w16 + (size_t)10 * WBIG;
    w[11] = w16 + (size_t)10 * WBIG + WSML;

    CPack cp;
    for (int i = 0; i < 12; i++) { cp.src[i] = wsrc[i]; cp.dst[i] = w[i]; cp.cnt[i] = (i < 10) ? WBIG : WSML; }
    cp.src[12] = x_pol; cp.dst[12] = xp16; cp.cnt[12] = NPOL * 64;
    cp.src[13] = x_stk; cp.dst[13] = xs16; cp.cnt[13] = NSTK * 64;

    const int PB = PROWS / 128;
    const int SB = SROWS / 128;

    auto prob = [](const __half* X0, const __half* W0, const __half* X1, const __half* W1,
                   const float* bias, const __half* C0, __half* C,
                   int M, int K, int npair, int dorelu) {
        GProb g; g.X0 = X0; g.W0 = W0; g.X1 = X1; g.W1 = W1;
        g.bias = bias; g.C0 = C0; g.C = C; g.M = M; g.K = K; g.npair = npair; g.dorelu = dorelu;
        return g;
    };

    // CSR stream: s2 when available, else default (sequential)
    cudaStream_t sc = use2 ? s2 : (cudaStream_t)0;

    // ---- fork: CSR build on sc, converts + projections on main stream ----
    if (use2) {
        cudaEventRecord(ev[0], 0);
        cudaStreamWaitEvent(s2, ev[0], 0);
    }
    zero2_kernel<<<64, 256, 0, sc>>>(cnt_ps, NSTK, cnt_sp, NPOL);
    histo2_kernel<<<400, 256, 0, sc>>>(eps_dst, cnt_ps, esp_dst, cnt_sp, EDG);
    exscan2_kernel<<<2, 1024, 0, sc>>>(cnt_ps, NSTK, off_ps, cur_ps, cnt_sp, NPOL, off_sp, cur_sp);
    scatter2_kernel<<<400, 256, 0, sc>>>(eps_src, eps_dst, cur_ps, src_ps,
                                         esp_src, esp_dst, cur_sp, src_sp, EDG);
    if (use2) cudaEventRecord(ev[1], s2);

    convert_all_kernel<<<dim3(256, 14), 256>>>(cp);
    {
        GProb a = prob(xp16, w[10], nullptr, nullptr, bp, nullptr, pA, NPOL, 64, 1, 1);
        GProb b = prob(xs16, w[11], nullptr, nullptr, bs, nullptr, sA, NSTK, 64, 1, 1);
        gemm_fp16_dual<<<dim3(PB + SB, 4), 256, SMG_TOT>>>(a, b, PB);
    }
    if (use2) cudaStreamWaitEvent(0, ev[1], 0);   // join

    // ---- layer 1: agg_ps on s2 concurrent with tmp GEMM + agg_sp ----
    if (use2) {
        cudaEventRecord(ev[2], 0);
        cudaStreamWaitEvent(s2, ev[2], 0);
    }
    agg_mean_kernel<<<NSTK, 128, 0, sc>>>(pA, off_ps, src_ps, sC);    // mean_ps(hp)
    if (use2) cudaEventRecord(ev[3], s2);

    {
        GProb a = prob(sA, w[2], nullptr, nullptr, nullptr, nullptr, sD, NSTK, 512, 1, 0);
        gemm_fp16_dual<<<dim3(SB, 4), 256, SMG_TOT>>>(a, a, SB);      // tmp1 = hs @ c1_sp_Wl
    }
    agg_mean_kernel<<<NPOL, 128>>>(sD, off_sp, src_sp, pC);           // mean_sp(tmp1)
    if (use2) cudaStreamWaitEvent(0, ev[3], 0);
    {
        GProb a = prob(sC, w[0], sA, w[1], c1_ps_bl, nullptr, sB, NSTK, 512, 2, 1);
        GProb b = prob(pA, w[3], nullptr, nullptr, c1_sp_bl, pC, pB, NPOL, 512, 1, 1);
        gemm_fp16_dual<<<dim3(SB + PB, 4), 256, SMG_TOT>>>(a, b, SB);
    }

    // ---- layer 2 ----
    if (use2) {
        cudaEventRecord(ev[4], 0);
        cudaStreamWaitEvent(s2, ev[4], 0);
    }
    agg_mean_kernel<<<NSTK, 128, 0, sc>>>(pB, off_ps, src_ps, sC);
    if (use2) cudaEventRecord(ev[5], s2);

    {
        GProb a = prob(sB, w[6], nullptr, nullptr, nullptr, nullptr, sD, NSTK, 512, 1, 0);
        gemm_fp16_dual<<<dim3(SB, 4), 256, SMG_TOT>>>(a, a, SB);      // tmp2
    }
    agg_mean_kernel<<<NPOL, 128>>>(sD, off_sp, src_sp, pC);
    if (use2) cudaStreamWaitEvent(0, ev[5], 0);
    {
        GProb a = prob(sC, w[4], sB, w[5], c2_ps_bl, nullptr, sA, NSTK, 512, 2, 1);
        GProb b = prob(pB, w[7], nullptr, nullptr, c2_sp_bl, pC, pA, NPOL, 512, 1, 1);
        gemm_fp16_dual<<<dim3(SB + PB, 4), 256, SMG_TOT>>>(a, b, SB);
    }

    // ---- decoder factorization (merged) ----
    {
        GProb a = prob(pA, w[8], nullptr, nullptr, nullptr, nullptr, pB, NPOL, 512, 1, 0);
        GProb b = prob(sA, w[9], nullptr, nullptr, nullptr, nullptr, sB, NSTK, 512, 1, 0);
        gemm_fp16_dual<<<dim3(PB + SB, 4), 256, SMG_TOT>>>(a, b, PB);
    }

    // ---- fused per-edge decoder ----
    edge_decode_kernel<<<2048, 256>>>(pB, sB, attr,
                                      d1_W + (size_t)1024 * HID,
                                      d1_W + (size_t)1025 * HID,
                                      d1_b, d2_W, d2_b, trow, tcol, out);
}

// round 16
// speedup vs baseline: 1.0964x; 1.0233x over previous
#include <cuda_runtime.h>
#include <cuda_fp16.h>
#include <mma.h>
#include <cstdint>

using namespace nvcuda;

#define NPOL 20000
#define NSTK 10000
#define EDG  400000
#define HID  512
#define NC   3

#define PROWS 20096
#define SROWS 10112

#define WBIG (512 * 512)
#define WSML (64 * 512)

// ---------------- device scratch ----------------
__device__ __half g_pA[(size_t)PROWS * HID];
__device__ __half g_pB[(size_t)PROWS * HID];
__device__ __half g_pC[(size_t)PROWS * HID];
__device__ __half g_sA[(size_t)SROWS * HID];
__device__ __half g_sB[(size_t)SROWS * HID];
__device__ __half g_sC[(size_t)SROWS * HID];
__device__ __half g_sD[(size_t)SROWS * HID];

__device__ __half g_w16[10 * WBIG + 2 * WSML];
__device__ __half g_xp16[(size_t)NPOL * 64];
__device__ __half g_xs16[(size_t)NSTK * 64];

__device__ int g_cnt_ps[NSTK];
__device__ int g_off_ps[NSTK + 1];
__device__ int g_cur_ps[NSTK];
__device__ int g_src_ps[EDG];

__device__ int g_cnt_sp[NPOL];
__device__ int g_off_sp[NPOL + 1];
__device__ int g_cur_sp[NPOL];
__device__ int g_src_sp[EDG];

// ---------------- f32 -> f16 converts ----------------
struct CPack {
    const float* src[14];
    __half*      dst[14];
    int          cnt[14];
};

__global__ __launch_bounds__(256) void convert_all_kernel(CPack p) {
    int s = blockIdx.y;
    const float4* src = reinterpret_cast<const float4*>(p.src[s]);
    __half2* dst = reinterpret_cast<__half2*>(p.dst[s]);
    int n4 = p.cnt[s] >> 2;
    for (int i = blockIdx.x * blockDim.x + threadIdx.x; i < n4; i += gridDim.x * blockDim.x) {
        float4 v = src[i];
        dst[2 * i]     = __floats2half2_rn(v.x, v.y);
        dst[2 * i + 1] = __floats2half2_rn(v.z, v.w);
    }
}

// ---------------- CSR build ----------------
__global__ void zero2_kernel(int* a, int na, int* b, int nb) {
    int i  = blockIdx.x * blockDim.x + threadIdx.x;
    int st = gridDim.x * blockDim.x;
    for (int j = i; j < na; j += st) a[j] = 0;
    for (int j = i; j < nb; j += st) b[j] = 0;
}

__global__ void histo2_kernel(const int* __restrict__ d0, int* c0,
                              const int* __restrict__ d1, int* c1, int n) {
    int i  = blockIdx.x * blockDim.x + threadIdx.x;
    int st = gridDim.x * blockDim.x;
    for (int e = i; e < n; e += st) {
        atomicAdd(&c0[d0[e]], 1);
        atomicAdd(&c1[d1[e]], 1);
    }
}

__global__ __launch_bounds__(1024) void exscan2_kernel(
    const int* __restrict__ cnt0, int n0, int* off0, int* cur0,
    const int* __restrict__ cnt1, int n1, int* off1, int* cur1) {
    const int* cnt = blockIdx.x ? cnt1 : cnt0;
    int  n   = blockIdx.x ? n1 : n0;
    int* off = blockIdx.x ? off1 : off0;
    int* cur = blockIdx.x ? cur1 : cur0;

    __shared__ int sWarp[32];
    __shared__ int sTotal;
    __shared__ int sCarry;
    int tid  = threadIdx.x;
    int wid  = tid >> 5;
    int lane = tid & 31;
    if (tid == 0) sCarry = 0;
    __syncthreads();

    for (int base = 0; base < n; base += 1024) {
        int i = base + tid;
        int v = (i < n) ? cnt[i] : 0;
        int incl = v;
        #pragma unroll
        for (int o = 1; o < 32; o <<= 1) {
            int t = __shfl_up_sync(0xffffffffu, incl, o);
            if (lane >= o) incl += t;
        }
        if (lane == 31) sWarp[wid] = incl;
        __syncthreads();
        if (wid == 0) {
            int wv = sWarp[lane];
            int wi = wv;
            #pragma unroll
            for (int o = 1; o < 32; o <<= 1) {
                int t = __shfl_up_sync(0xffffffffu, wi, o);
                if (lane >= o) wi += t;
            }
            sWarp[lane] = wi - wv;
            if (lane == 31) sTotal = wi;
        }
        __syncthreads();
        int carry = sCarry;
        if (i < n) {
            int ex = carry + sWarp[wid] + incl - v;
            off[i] = ex;
            cur[i] = ex;
        }
        __syncthreads();
        if (tid == 0) sCarry = carry + sTotal;
        __syncthreads();
    }
    if (tid == 0) off[n] = sCarry;
}

__global__ void scatter2_kernel(const int* __restrict__ s0, const int* __restrict__ dd0,
                                int* cur0, int* o0,
                                const int* __restrict__ s1, const int* __restrict__ dd1,
                                int* cur1, int* o1, int n) {
    int i  = blockIdx.x * blockDim.x + threadIdx.x;
    int st = gridDim.x * blockDim.x;
    for (int e = i; e < n; e += st) {
        int p0 = atomicAdd(&cur0[dd0[e]], 1);
        o0[p0] = s0[e];
        int p1 = atomicAdd(&cur1[dd1[e]], 1);
        o1[p1] = s1[e];
    }
}

// ---------------- mean aggregation over CSR ----------------
__global__ __launch_bounds__(128) void agg_mean_kernel(
    const __half* __restrict__ X, const int* __restrict__ off,
    const int* __restrict__ srcs, __half* __restrict__ out) {
    int d   = blockIdx.x;
    int tid = threadIdx.x;
    int beg = off[d];
    int end = off[d + 1];

    __shared__ int sIdx[128];
    float a0 = 0.f, a1 = 0.f, a2 = 0.f, a3 = 0.f;

    for (int cb = beg; cb < end; cb += 128) {
        int m = min(128, end - cb);
        if (tid < m) sIdx[tid] = srcs[cb + tid];
        __syncthreads();
        int j = 0;
        for (; j + 4 <= m; j += 4) {
            uint2 v0 = reinterpret_cast<const uint2*>(X + (size_t)sIdx[j]     * HID)[tid];
            uint2 v1 = reinterpret_cast<const uint2*>(X + (size_t)sIdx[j + 1] * HID)[tid];
            uint2 v2 = reinterpret_cast<const uint2*>(X + (size_t)sIdx[j + 2] * HID)[tid];
            uint2 v3 = reinterpret_cast<const uint2*>(X + (size_t)sIdx[j + 3] * HID)[tid];
            float2 f;
            f = __half22float2(*reinterpret_cast<__half2*>(&v0.x)); a0 += f.x; a1 += f.y;
            f = __half22float2(*reinterpret_cast<__half2*>(&v0.y)); a2 += f.x; a3 += f.y;
            f = __half22float2(*reinterpret_cast<__half2*>(&v1.x)); a0 += f.x; a1 += f.y;
            f = __half22float2(*reinterpret_cast<__half2*>(&v1.y)); a2 += f.x; a3 += f.y;
            f = __half22float2(*reinterpret_cast<__half2*>(&v2.x)); a0 += f.x; a1 += f.y;
            f = __half22float2(*reinterpret_cast<__half2*>(&v2.y)); a2 += f.x; a3 += f.y;
            f = __half22float2(*reinterpret_cast<__half2*>(&v3.x)); a0 += f.x; a1 += f.y;
            f = __half22float2(*reinterpret_cast<__half2*>(&v3.y)); a2 += f.x; a3 += f.y;
        }
        for (; j < m; j++) {
            uint2 v = reinterpret_cast<const uint2*>(X + (size_t)sIdx[j] * HID)[tid];
            float2 f;
            f = __half22float2(*reinterpret_cast<__half2*>(&v.x)); a0 += f.x; a1 += f.y;
            f = __half22float2(*reinterpret_cast<__half2*>(&v.y)); a2 += f.x; a3 += f.y;
        }
        __syncthreads();
    }
    float inv = (end > beg) ? 1.0f / (float)(end - beg) : 0.0f;
    uint2 ov;
    *reinterpret_cast<__half2*>(&ov.x) = __floats2half2_rn(a0 * inv, a1 * inv);
    *reinterpret_cast<__half2*>(&ov.y) = __floats2half2_rn(a2 * inv, a3 * inv);
    reinterpret_cast<uint2*>(out + (size_t)d * HID)[tid] = ov;
}

// ---------------- cp.async helpers ----------------
__device__ __forceinline__ void cp_async16(void* dst, const void* src, bool pred) {
    uint32_t s = (uint32_t)__cvta_generic_to_shared(dst);
    int n = pred ? 16 : 0;
    asm volatile("cp.async.cg.shared.global [%0], [%1], 16, %2;\n" :: "r"(s), "l"(src), "r"(n));
}
__device__ __forceinline__ void cp_commit() { asm volatile("cp.async.commit_group;\n"); }
template <int N>
__device__ __forceinline__ void cp_wait() { asm volatile("cp.async.wait_group %0;\n" :: "n"(N)); }

// ---------------- fp16 WMMA GEMM (dual-problem), fp16 output — frozen R11 config ----
#define XLDH 40
#define WLDH 136
#define SLDF 20
#define SMO_XS    0
#define SMO_WS    40960
#define SMO_BIAS  75776
#define SMO_STAGE 76288
#define SMG_TOT   86528

struct GProb {
    const __half* X0; const __half* W0;
    const __half* X1; const __half* W1;
    const float*  bias; const __half* C0;
    __half* C;
    int M, K, npair, dorelu;
};

__global__ __launch_bounds__(256) void gemm_fp16_dual(GProb pa, GProb pb, int split) {
    extern __shared__ __align__(16) char dsm[];
    __half (*Xs)[128][XLDH] = reinterpret_cast<__half(*)[128][XLDH]>(dsm + SMO_XS);
    __half (*Ws)[32][WLDH]  = reinterpret_cast<__half(*)[32][WLDH]>(dsm + SMO_WS);
    float* s_bias  = reinterpret_cast<float*>(dsm + SMO_BIAS);
    float* s_stage = reinterpret_cast<float*>(dsm + SMO_STAGE);

    const bool  first = (int)blockIdx.x < split;
    const GProb P     = first ? pa : pb;
    const int   bx    = first ? blockIdx.x : (blockIdx.x - split);

    const int row0 = bx * 128;
    const int n0   = blockIdx.y * 128;
    const int tid  = threadIdx.x;
    const int warp = tid >> 5;
    const int lane = tid & 31;
    const int wm   = warp >> 1;
    const int wn   = warp & 1;

    if (tid < 128) s_bias[tid] = P.bias ? P.bias[n0 + tid] : 0.0f;

    wmma::fragment<wmma::accumulator, 16, 16, 16, float> acc[2][4];
    #pragma unroll
    for (int i = 0; i < 2; i++)
        #pragma unroll
        for (int j = 0; j < 4; j++)
            wmma::fill_fragment(acc[i][j], 0.0f);

    const int CK = P.K >> 5;
    const int T  = P.npair * CK;
    const int K  = P.K;
    const int M  = P.M;

    auto load_chunk = [&](int c, int buf) {
        int pair = (c >= CK) ? 1 : 0;
        const __half* X = pair ? P.X1 : P.X0;
        const __half* W = pair ? P.W1 : P.W0;
        int kk = (c - pair * CK) * 32;
        #pragma unroll
        for (int q = 0; q < 2; q++) {
            int u = tid + q * 256;
            int r = u >> 2, cu = u & 3;
            int rg = row0 + r;
            cp_async16(&Xs[buf][r][cu * 8], X + (size_t)rg * K + kk + cu * 8, rg < M);
        }
        #pragma unroll
        for (int q = 0; q < 2; q++) {
            int u = tid + q * 256;
            int r = u >> 4, cu = u & 15;
            cp_async16(&Ws[buf][r][cu * 8], W + (size_t)(kk + r) * HID + n0 + cu * 8, true);
        }
        cp_commit();
    };

    auto compute = [&](int buf) {
        #pragma unroll
        for (int kk = 0; kk < 32; kk += 16) {
            wmma::fragment<wmma::matrix_a, 16, 16, 16, __half, wmma::row_major> a[2];
            wmma::fragment<wmma::matrix_b, 16, 16, 16, __half, wmma::row_major> b[4];
            #pragma unroll
            for (int i = 0; i < 2; i++)
                wmma::load_matrix_sync(a[i], &Xs[buf][wm * 32 + i * 16][kk], XLDH);
            #pragma unroll
            for (int j = 0; j < 4; j++)
                wmma::load_matrix_sync(b[j], &Ws[buf][kk][wn * 64 + j * 16], WLDH);
            #pragma unroll
            for (int i = 0; i < 2; i++)
                #pragma unroll
                for (int j = 0; j < 4; j++)
                    wmma::mma_sync(acc[i][j], a[i], b[j], acc[i][j]);
        }
    };

    load_chunk(0, 0);
    if (T > 1) load_chunk(1, 1);
    if (T > 2) load_chunk(2, 2);
    for (int t = 0; t < T; t++) {
        if (t + 2 < T)      cp_wait<2>();
        else if (t + 1 < T) cp_wait<1>();
        else                cp_wait<0>();
        __syncthreads();
        compute(t & 3);
        if (t + 3 < T) load_chunk(t + 3, (t + 3) & 3);
    }

    float* stw = s_stage + warp * (16 * SLDF);
    const int lr = lane >> 1;
    const int lc = (lane & 1) * 8;
    #pragma unroll
    for (int i = 0; i < 2; i++) {
        #pragma unroll
        for (int j = 0; j < 4; j++) {
            wmma::store_matrix_sync(stw, acc[i][j], SLDF, wmma::mem_row_major);
            __syncwarp();
            int grow = row0 + wm * 32 + i * 16 + lr;
            int bcol = wn * 64 + j * 16 + lc;
            const float* sp = stw + lr * SLDF + lc;
            float v[8];
            #pragma unroll
            for (int t = 0; t < 8; t++) v[t] = sp[t] + s_bias[bcol + t];
            if (P.C0) {
                uint4 cz = *reinterpret_cast<const uint4*>(P.C0 + (size_t)grow * HID + n0 + bcol);
                float2 c0 = __half22float2(*reinterpret_cast<__half2*>(&cz.x));
                float2 c1 = __half22float2(*reinterpret_cast<__half2*>(&cz.y));
                float2 c2 = __half22float2(*reinterpret_cast<__half2*>(&cz.z));
                float2 c3 = __half22float2(*reinterpret_cast<__half2*>(&cz.w));
                v[0] += c0.x; v[1] += c0.y; v[2] += c1.x; v[3] += c1.y;
                v[4] += c2.x; v[5] += c2.y; v[6] += c3.x; v[7] += c3.y;
            }
            if (P.dorelu) {
                #pragma unroll
                for (int t = 0; t < 8; t++) v[t] = fmaxf(v[t], 0.0f);
            }
            uint4 ov;
            *reinterpret_cast<__half2*>(&ov.x) = __floats2half2_rn(v[0], v[1]);
            *reinterpret_cast<__half2*>(&ov.y) = __floats2half2_rn(v[2], v[3]);
            *reinterpret_cast<__half2*>(&ov.z) = __floats2half2_rn(v[4], v[5]);
            *reinterpret_cast<__half2*>(&ov.w) = __floats2half2_rn(v[6], v[7]);
            *reinterpret_cast<uint4*>(P.C + (size_t)grow * HID + n0 + bcol) = ov;
            __syncwarp();
        }
    }
}

// ---------------- fused per-edge decoder (fp16 A/B via uint4, fp32 math) ----------------
__global__ __launch_bounds__(256) void edge_decode_kernel(
    const __half* __restrict__ Aa, const __half* __restrict__ Bb,
    const float* __restrict__ attr,
    const float* __restrict__ w0, const float* __restrict__ w1,
    const float* __restrict__ b1,
    const float* __restrict__ d2W, const float* __restrict__ d2b,
    const int* __restrict__ erow, const int* __restrict__ ecol,
    float* __restrict__ out) {
    __shared__ float s_w0[512], s_w1[512], s_b[512], s_d0[512], s_d1[512], s_d2[512];
    int tid = threadIdx.x;
    for (int i = tid; i < HID; i += 256) {
        s_w0[i] = w0[i];
        s_w1[i] = w1[i];
        s_b[i]  = b1[i];
        s_d0[i] = d2W[i * 3 + 0];
        s_d1[i] = d2W[i * 3 + 1];
        s_d2[i] = d2W[i * 3 + 2];
    }
    __syncthreads();
    float db0 = d2b[0], db1 = d2b[1], db2 = d2b[2];
    int lane = tid & 31;
    int warp = tid >> 5;

    for (int e = blockIdx.x * 8 + warp; e < EDG; e += gridDim.x * 8) {
        int r = erow[e];
        int c = ecol[e];
        float a0 = attr[2 * e];
        float a1 = attr[2 * e + 1];
        const uint4* A4 = reinterpret_cast<const uint4*>(Aa + (size_t)r * HID);
        const uint4* B4 = reinterpret_cast<const uint4*>(Bb + (size_t)c * HID);
        float s0 = 0.f, s1 = 0.f, s2 = 0.f;
        #pragma unroll
        for (int k = 0; k < 2; k++) {
            int q = k * 32 + lane;
            uint4 au = A4[q], bu = B4[q];
            int base = q * 8;
            const uint32_t* ap = reinterpret_cast<const uint32_t*>(&au);
            const uint32_t* bp = reinterpret_cast<const uint32_t*>(&bu);
            #pragma unroll
            for (int h2 = 0; h2 < 4; h2++) {
                float2 fa = __half22float2(*reinterpret_cast<const __half2*>(&ap[h2]));
                float2 fb = __half22float2(*reinterpret_cast<const __half2*>(&bp[h2]));
                int i0 = base + h2 * 2;
                float hv;
                hv = fmaxf(fa.x + fb.x + a0 * s_w0[i0] + a1 * s_w1[i0] + s_b[i0], 0.f);
                s0 += hv * s_d0[i0]; s1 += hv * s_d1[i0]; s2 += hv * s_d2[i0];
                hv = fmaxf(fa.y + fb.y + a0 * s_w0[i0 + 1] + a1 * s_w1[i0 + 1] + s_b[i0 + 1], 0.f);
                s0 += hv * s_d0[i0 + 1]; s1 += hv * s_d1[i0 + 1]; s2 += hv * s_d2[i0 + 1];
            }
        }
        #pragma unroll
        for (int o = 16; o > 0; o >>= 1) {
            s0 += __shfl_xor_sync(0xffffffffu, s0, o);
            s1 += __shfl_xor_sync(0xffffffffu, s1, o);
            s2 += __shfl_xor_sync(0xffffffffu, s2, o);
        }
        if (lane == 0) {
            out[(size_t)e * 3 + 0] = s0 + db0;
            out[(size_t)e * 3 + 1] = s1 + db1;
            out[(size_t)e * 3 + 2] = s2 + db2;
        }
    }
}

// ---------------- host launch ----------------
extern "C" void kernel_launch(void* const* d_in, const int* in_sizes, int n_in,
                              void* d_out, int out_size) {
    (void)in_sizes; (void)n_in; (void)out_size;

    const float* x_pol = (const float*)d_in[0];
    const float* x_stk = (const float*)d_in[1];
    const float* attr  = (const float*)d_in[2];
    const float* Wp    = (const float*)d_in[3];
    const float* bp    = (const float*)d_in[4];
    const float* Ws    = (const float*)d_in[5];
    const float* bs    = (const float*)d_in[6];
    const float* c1_ps_Wl = (const float*)d_in[7];
    const float* c1_ps_bl = (const float*)d_in[8];
    const float* c1_ps_Wr = (const float*)d_in[9];
    const float* c1_sp_Wl = (const float*)d_in[10];
    const float* c1_sp_bl = (const float*)d_in[11];
    const float* c1_sp_Wr = (const float*)d_in[12];
    const float* c2_ps_Wl = (const float*)d_in[13];
    const float* c2_ps_bl = (const float*)d_in[14];
    const float* c2_ps_Wr = (const float*)d_in[15];
    const float* c2_sp_Wl = (const float*)d_in[16];
    const float* c2_sp_bl = (const float*)d_in[17];
    const float* c2_sp_Wr = (const float*)d_in[18];
    const float* d1_W  = (const float*)d_in[19];
    const float* d1_b  = (const float*)d_in[20];
    const float* d2_W  = (const float*)d_in[21];
    const float* d2_b  = (const float*)d_in[22];
    const int* eps_src = (const int*)d_in[23];
    const int* eps_dst = (const int*)d_in[24];
    const int* esp_src = (const int*)d_in[25];
    const int* esp_dst = (const int*)d_in[26];
    const int* trow    = (const int*)d_in[27];
    const int* tcol    = (const int*)d_in[28];
    float* out = (float*)d_out;

    void* p;
    cudaGetSymbolAddress(&p, g_pA);     __half* pA = (__half*)p;
    cudaGetSymbolAddress(&p, g_pB);     __half* pB = (__half*)p;
    cudaGetSymbolAddress(&p, g_pC);     __half* pC = (__half*)p;
    cudaGetSymbolAddress(&p, g_sA);     __half* sA = (__half*)p;
    cudaGetSymbolAddress(&p, g_sB);     __half* sB = (__half*)p;
    cudaGetSymbolAddress(&p, g_sC);     __half* sC = (__half*)p;
    cudaGetSymbolAddress(&p, g_sD);     __half* sD = (__half*)p;
    cudaGetSymbolAddress(&p, g_w16);    __half* w16 = (__half*)p;
    cudaGetSymbolAddress(&p, g_xp16);   __half* xp16 = (__half*)p;
    cudaGetSymbolAddress(&p, g_xs16);   __half* xs16 = (__half*)p;
    cudaGetSymbolAddress(&p, g_cnt_ps); int* cnt_ps = (int*)p;
    cudaGetSymbolAddress(&p, g_off_ps); int* off_ps = (int*)p;
    cudaGetSymbolAddress(&p, g_cur_ps); int* cur_ps = (int*)p;
    cudaGetSymbolAddress(&p, g_src_ps); int* src_ps = (int*)p;
    cudaGetSymbolAddress(&p, g_cnt_sp); int* cnt_sp = (int*)p;
    cudaGetSymbolAddress(&p, g_off_sp); int* off_sp = (int*)p;
    cudaGetSymbolAddress(&p, g_cur_sp); int* cur_sp = (int*)p;
    cudaGetSymbolAddress(&p, g_src_sp); int* src_sp = (int*)p;

    cudaFuncSetAttribute(gemm_fp16_dual, cudaFuncAttributeMaxDynamicSharedMemorySize, SMG_TOT);

    static cudaStream_t s2 = nullptr;
    static cudaEvent_t ev[8];
    static bool tried = false, use2 = false;
    if (!tried) {
        tried = true;
        if (cudaStreamCreateWithFlags(&s2, cudaStreamNonBlocking) == cudaSuccess) {
            use2 = true;
            for (int i = 0; i < 8; i++) {
                if (cudaEventCreateWithFlags(&ev[i], cudaEventDisableTiming) != cudaSuccess) {
                    use2 = false;
                    break;
                }
            }
        }
    }

    __half* w[12];
    const float* wsrc[12] = {c1_ps_Wl, c1_ps_Wr, c1_sp_Wl, c1_sp_Wr,
                             c2_ps_Wl, c2_ps_Wr, c2_sp_Wl, c2_sp_Wr,
                             d1_W, d1_W + (size_t)512 * HID, Wp, Ws};
    for (int i = 0; i < 10; i++) w[i] = w16 + (size_t)i * WBIG;
    w[10] = w16 + (size_t)10 * WBIG;
    w[11] = w16 + (size_t)10 * WBIG + WSML;

    CPack cp;
    for (int i = 0; i < 12; i++) { cp.src[i] = wsrc[i]; cp.dst[i] = w[i]; cp.cnt[i] = (i < 10) ? WBIG : WSML; }
    cp.src[12] = x_pol; cp.dst[12] = xp16; cp.cnt[12] = NPOL * 64;
    cp.src[13] = x_stk; cp.dst[13] = xs16; cp.cnt[13] = NSTK * 64;

    const int PB = PROWS / 128;
    const int SB = SROWS / 128;

    auto prob = [](const __half* X0, const __half* W0, const __half* X1, const __half* W1,
                   const float* bias, const __half* C0, __half* C,
                   int M, int K, int npair, int dorelu) {
        GProb g; g.X0 = X0; g.W0 = W0; g.X1 = X1; g.W1 = W1;
        g.bias = bias; g.C0 = C0; g.C = C; g.M = M; g.K = K; g.npair = npair; g.dorelu = dorelu;
        return g;
    };

    cudaStream_t sc = use2 ? s2 : (cudaStream_t)0;

    // ---- fork: CSR build on sc; converts + projections + tmp1 on main ----
    if (use2) {
        cudaEventRecord(ev[0], 0);
        cudaStreamWaitEvent(s2, ev[0], 0);
    }
    zero2_kernel<<<64, 256, 0, sc>>>(cnt_ps, NSTK, cnt_sp, NPOL);
    histo2_kernel<<<400, 256, 0, sc>>>(eps_dst, cnt_ps, esp_dst, cnt_sp, EDG);
    exscan2_kernel<<<2, 1024, 0, sc>>>(cnt_ps, NSTK, off_ps, cur_ps, cnt_sp, NPOL, off_sp, cur_sp);
    scatter2_kernel<<<400, 256, 0, sc>>>(eps_src, eps_dst, cur_ps, src_ps,
                                         esp_src, esp_dst, cur_sp, src_sp, EDG);
    if (use2) cudaEventRecord(ev[1], s2);

    convert_all_kernel<<<dim3(256, 14), 256>>>(cp);
    {
        GProb a = prob(xp16, w[10], nullptr, nullptr, bp, nullptr, pA, NPOL, 64, 1, 1);
        GProb b = prob(xs16, w[11], nullptr, nullptr, bs, nullptr, sA, NSTK, 64, 1, 1);
        gemm_fp16_dual<<<dim3(PB + SB, 4), 256, SMG_TOT>>>(a, b, PB);
    }
    // tmp1 needs only proj output + converted weights — launch before CSR join
    {
        GProb a = prob(sA, w[2], nullptr, nullptr, nullptr, nullptr, sD, NSTK, 512, 1, 0);
        gemm_fp16_dual<<<dim3(SB, 4), 256, SMG_TOT>>>(a, a, SB);
    }
    if (use2) cudaStreamWaitEvent(0, ev[1], 0);   // join CSR

    // ---- layer 1: s2 = agg_ps -> hs1 GEMM ; main = agg_sp -> hp1 GEMM ----
    if (use2) {
        cudaEventRecord(ev[2], 0);
        cudaStreamWaitEvent(s2, ev[2], 0);
    }
    agg_mean_kernel<<<NSTK, 128, 0, sc>>>(pA, off_ps, src_ps, sC);
    {
        GProb a = prob(sC, w[0], sA, w[1], c1_ps_bl, nullptr, sB, NSTK, 512, 2, 1);
        gemm_fp16_dual<<<dim3(SB, 4), 256, SMG_TOT, sc>>>(a, a, SB);      // hs1
    }
    if (use2) cudaEventRecord(ev[3], s2);

    agg_mean_kernel<<<NPOL, 128>>>(sD, off_sp, src_sp, pC);               // mean_sp(tmp1)
    {
        GProb a = prob(pA, w[3], nullptr, nullptr, c1_sp_bl, pC, pB, NPOL, 512, 1, 1);
        gemm_fp16_dual<<<dim3(PB, 4), 256, SMG_TOT>>>(a, a, PB);          // hp1
    }
    if (use2) cudaStreamWaitEvent(0, ev[3], 0);

    // tmp2 = hs1 @ c2_sp_Wl (needs sB from s2's hs1 — after join)
    {
        GProb a = prob(sB, w[6], nullptr, nullptr, nullptr, nullptr, sD, NSTK, 512, 1, 0);
        gemm_fp16_dual<<<dim3(SB, 4), 256, SMG_TOT>>>(a, a, SB);
    }

    // ---- layer 2: s2 = agg_ps -> hs2 GEMM ; main = agg_sp -> hp2 GEMM ----
    if (use2) {
        cudaEventRecord(ev[4], 0);
        cudaStreamWaitEvent(s2, ev[4], 0);
    }
    agg_mean_kernel<<<NSTK, 128, 0, sc>>>(pB, off_ps, src_ps, sC);
    {
        GProb a = prob(sC, w[4], sB, w[5], c2_ps_bl, nullptr, sA, NSTK, 512, 2, 1);
        gemm_fp16_dual<<<dim3(SB, 4), 256, SMG_TOT, sc>>>(a, a, SB);      // hs2
    }
    // B factorization also on s2 (depends only on sA just computed there)
    {
        GProb b = prob(sA, w[9], nullptr, nullptr, nullptr, nullptr, sB, NSTK, 512, 1, 0);
        gemm_fp16_dual<<<dim3(SB, 4), 256, SMG_TOT, sc>>>(b, b, SB);      // B
    }
    if (use2) cudaEventRecord(ev[5], s2);

    agg_mean_kernel<<<NPOL, 128>>>(sD, off_sp, src_sp, pC);
    {
        GProb a = prob(pB, w[7], nullptr, nullptr, c2_sp_bl, pC, pA, NPOL, 512, 1, 1);
        gemm_fp16_dual<<<dim3(PB, 4), 256, SMG_TOT>>>(a, a, PB);          // hp2
    }
    // A factorization on main (depends only on pA just computed here)
    {
        GProb a = prob(pA, w[8], nullptr, nullptr, nullptr, nullptr, pB, NPOL, 512, 1, 0);
        gemm_fp16_dual<<<dim3(PB, 4), 256, SMG_TOT>>>(a, a, PB);          // A
    }
    if (use2) cudaStreamWaitEvent(0, ev[5], 0);   // join: B ready

    // ---- fused per-edge decoder ----
    edge_decode_kernel<<<2048, 256>>>(pB, sB, attr,
                                      d1_W + (size_t)1024 * HID,
                                      d1_W + (size_t)1025 * HID,
                                      d1_b, d2_W, d2_b, trow, tcol, out);
}